// round 5
// baseline (speedup 1.0000x reference)
#include <cuda_runtime.h>
#include <cuda_fp16.h>
#include <cstdint>

#define NN 50000
#define EE 400000
#define FF 256
#define HH 512
#define CC 3
#define NPAD 50048              // 391 * 128

// ---------------- device scratch ----------------
__device__ float g_X[(size_t)NPAD * HH];     // fp32 activations
__device__ __half g_Ah[(size_t)NPAD * HH];   // agg output hi (fp16)
__device__ __half g_Am[(size_t)NPAD * HH];   // agg output residual (fp16)
__device__ __half g_Wh[(size_t)13 * HH * HH];  // transposed [n][k] hi
__device__ __half g_Wm[(size_t)13 * HH * HH];  // transposed [n][k] residual
__device__ float g_S[(size_t)NN * CC];
__device__ float g_dinv[NN];
__device__ float g_coef[EE + NN];   // CSR coefs incl. self loops
__device__ int   g_col[EE + NN];
__device__ int   g_srcA[EE];
__device__ int   g_dstA[EE];
__device__ int   g_cnt[NN];
__device__ int   g_fill[NN];
__device__ int   g_rowptr[NN + 1];
__device__ unsigned g_is32;

// ---------------- preprocessing ----------------
__global__ void detect_kernel(const unsigned* __restrict__ w) {
    unsigned local = 0;
    for (int i = blockIdx.x * blockDim.x + threadIdx.x; i < EE;
         i += gridDim.x * blockDim.x)
        local |= w[2 * i + 1];
    #pragma unroll
    for (int off = 16; off; off >>= 1)
        local |= __shfl_xor_sync(0xffffffffu, local, off);
    if ((threadIdx.x & 31) == 0 && local) atomicOr(&g_is32, 1u);
}

__global__ void convert_count_kernel(const void* __restrict__ ei) {
    int e = blockIdx.x * blockDim.x + threadIdx.x;
    if (e >= EE) return;
    int s, d;
    if (g_is32) {
        const int* p = (const int*)ei;
        s = p[e]; d = p[EE + e];
    } else {
        const long long* p = (const long long*)ei;
        s = (int)p[e]; d = (int)p[EE + e];
    }
    g_srcA[e] = s; g_dstA[e] = d;
    atomicAdd(&g_cnt[d], 1);
}

// single block: exclusive scan of (cnt+1), dinv, self-loop CSR entries
__global__ void scan_kernel() {
    __shared__ int s[1024];
    const int T = 1024;
    int tid = threadIdx.x;
    int chunk = (NN + T - 1) / T;
    int beg = tid * chunk;
    int end = min(beg + chunk, NN);
    int sum = 0;
    for (int i = beg; i < end; i++) sum += g_cnt[i] + 1;
    s[tid] = sum;
    __syncthreads();
    for (int off = 1; off < T; off <<= 1) {
        int v = (tid >= off) ? s[tid - off] : 0;
        __syncthreads();
        s[tid] += v;
        __syncthreads();
    }
    int run = (tid > 0) ? s[tid - 1] : 0;
    for (int i = beg; i < end; i++) {
        int c = g_cnt[i];
        float di = rsqrtf((float)c + 1.0f);
        g_rowptr[i] = run;
        g_dinv[i] = di;
        g_col[run + c] = i;          // self-loop in last slot
        g_coef[run + c] = di * di;
        run += c + 1;
    }
    if (tid == T - 1) g_rowptr[NN] = run;
}

__global__ void fill_kernel() {
    int e = blockIdx.x * blockDim.x + threadIdx.x;
    if (e >= EE) return;
    int d = g_dstA[e], s = g_srcA[e];
    int pos = g_rowptr[d] + atomicAdd(&g_fill[d], 1);
    g_col[pos]  = s;
    g_coef[pos] = g_dinv[s] * g_dinv[d];
}

// ---------------- weight transpose + fp16 hi/residual split ----------------
__global__ void wsplit_kernel(const float* __restrict__ W0,
                              const float* __restrict__ Wr) {
    int L = blockIdx.y;
    int n = blockIdx.x;
    int K = (L == 0) ? FF : HH;
    const float* W = (L == 0) ? W0 : (Wr + (size_t)(L - 1) * HH * HH);
    size_t slot = (size_t)L * HH * HH;
    for (int k = threadIdx.x; k < K; k += blockDim.x) {
        float x = W[(size_t)k * HH + n];
        __half h = __float2half_rn(x);
        float r = x - __half2float(h);
        g_Wh[slot + (size_t)n * K + k] = h;
        g_Wm[slot + (size_t)n * K + k] = __float2half_rn(r);
    }
}

// ---------------- aggregation: fp16 hi/residual split output ----------------
template <int W4>
__global__ void agg_kernel(const float* __restrict__ X,
                           __half* __restrict__ Th,
                           __half* __restrict__ Tm, int sA) {
    int node = blockIdx.x;
    int t = threadIdx.x;
    const float4* Xv = (const float4*)X;
    float4 acc = make_float4(0.f, 0.f, 0.f, 0.f);
    int beg = g_rowptr[node], end = g_rowptr[node + 1];
    for (int e = beg; e < end; e++) {
        int s = g_col[e];
        float cf = g_coef[e];
        float4 v = Xv[(size_t)s * W4 + t];
        acc.x += cf * v.x; acc.y += cf * v.y;
        acc.z += cf * v.z; acc.w += cf * v.w;
    }
    float vals[4] = {acc.x, acc.y, acc.z, acc.w};
    unsigned hb[4], mb[4];
    #pragma unroll
    for (int i = 0; i < 4; i++) {
        __half h = __float2half_rn(vals[i]);
        float r = vals[i] - __half2float(h);
        __half m = __float2half_rn(r);
        hb[i] = (unsigned)__half_as_ushort(h);
        mb[i] = (unsigned)__half_as_ushort(m);
    }
    uint2 ph, pm;
    ph.x = hb[0] | (hb[1] << 16); ph.y = hb[2] | (hb[3] << 16);
    pm.x = mb[0] | (mb[1] << 16); pm.y = mb[2] | (mb[3] << 16);
    size_t off = (size_t)node * sA + 4 * t;
    *(uint2*)(Th + off) = ph;
    *(uint2*)(Tm + off) = pm;
}

// ---------------- HMMA fp16x2 GEMM ----------------
// C[M,512] = relu(A[M,K] @ W[K,512] + bias)
// Block 128x128, 8 warps (2M x 4N), warp tile 64x32, BK=32, double-buffered cp.async.
// Main term f32-acc; two correction terms f16-acc (2x rate).
#define APITCH_B 80          // bytes per smem row
#define ARR_B    10240       // bytes per array (128*80)
#define STAGE_B  40960       // 4 arrays
#define GSMEM_B  81920       // 2 stages

#define MMA_F32ACC(cc, A0, A1, A2, A3, B0, B1)                                \
    asm volatile(                                                             \
        "mma.sync.aligned.m16n8k16.row.col.f32.f16.f16.f32 "                  \
        "{%0,%1,%2,%3}, {%4,%5,%6,%7}, {%8,%9}, {%0,%1,%2,%3};"               \
        : "+f"(cc[0]), "+f"(cc[1]), "+f"(cc[2]), "+f"(cc[3])                  \
        : "r"(A0), "r"(A1), "r"(A2), "r"(A3), "r"(B0), "r"(B1))

#define MMA_F16ACC(dd, A0, A1, A2, A3, B0, B1)                                \
    asm volatile(                                                             \
        "mma.sync.aligned.m16n8k16.row.col.f16.f16.f16.f16 "                  \
        "{%0,%1}, {%2,%3,%4,%5}, {%6,%7}, {%0,%1};"                           \
        : "+r"(dd[0]), "+r"(dd[1])                                            \
        : "r"(A0), "r"(A1), "r"(A2), "r"(A3), "r"(B0), "r"(B1))

__global__ void __launch_bounds__(256, 2) gemm_mma_kernel(
    const __half* __restrict__ Ah, const __half* __restrict__ Am,
    const __half* __restrict__ Wh, const __half* __restrict__ Wm,
    const float* __restrict__ bias, float* __restrict__ Xout,
    int M, int K, int sA) {
    extern __shared__ char smb[];
    uint32_t sbase;
    asm("{ .reg .u64 t; cvta.to.shared.u64 t, %1; cvt.u32.u64 %0, t; }"
        : "=r"(sbase) : "l"(smb));

    const int tid = threadIdx.x;
    const int lane = tid & 31, wid = tid >> 5;
    const int g = lane >> 2, t4 = lane & 3;
    const int warpM = wid & 1, warpN = wid >> 1;
    const int mBase = blockIdx.x * 128, nBase = blockIdx.y * 128;
    const int nChunks = K >> 5;

    float acc[4][4][4];
    uint32_t acc16[4][4][2];
    #pragma unroll
    for (int i = 0; i < 4; i++)
        #pragma unroll
        for (int j = 0; j < 4; j++) {
            #pragma unroll
            for (int v = 0; v < 4; v++) acc[i][j][v] = 0.f;
            acc16[i][j][0] = 0u; acc16[i][j][1] = 0u;
        }

    #define STAGE_LOAD(buf, chunk) do {                                        \
        int k0 = (chunk) * 32;                                                 \
        uint32_t sb = sbase + (buf) * STAGE_B;                                 \
        _Pragma("unroll")                                                      \
        for (int h = 0; h < 2; h++) {                                          \
            int q = tid + h * 256;                                             \
            int row = q >> 2, c16 = q & 3;                                     \
            uint32_t ds = sb + row * APITCH_B + c16 * 16;                      \
            int gr = mBase + row;                                              \
            int vsz = (gr < M) ? 16 : 0;                                       \
            long long aoff = (long long)(gr < M ? gr : 0) * sA + k0 + c16 * 8; \
            asm volatile("cp.async.cg.shared.global [%0], [%1], 16, %2;"       \
                :: "r"(ds), "l"(Ah + aoff), "r"(vsz));                         \
            asm volatile("cp.async.cg.shared.global [%0], [%1], 16, %2;"       \
                :: "r"(ds + ARR_B), "l"(Am + aoff), "r"(vsz));                 \
            long long boff = (long long)(nBase + row) * K + k0 + c16 * 8;     \
            asm volatile("cp.async.cg.shared.global [%0], [%1], 16;"           \
                :: "r"(ds + 2 * ARR_B), "l"(Wh + boff));                       \
            asm volatile("cp.async.cg.shared.global [%0], [%1], 16;"           \
                :: "r"(ds + 3 * ARR_B), "l"(Wm + boff));                       \
        }                                                                      \
        asm volatile("cp.async.commit_group;");                                \
    } while (0)

    STAGE_LOAD(0, 0);

    for (int c = 0; c < nChunks; c++) {
        int b = c & 1;
        if (c + 1 < nChunks) {
            STAGE_LOAD(b ^ 1, c + 1);
            asm volatile("cp.async.wait_group 1;");
        } else {
            asm volatile("cp.async.wait_group 0;");
        }
        __syncthreads();

        const char* bufA = smb + b * STAGE_B;
        const char* bufB = bufA + 2 * ARR_B;
        #pragma unroll
        for (int kk = 0; kk < 32; kk += 16) {
            uint32_t bh[4][2], bm[4][2];
            #pragma unroll
            for (int j = 0; j < 4; j++) {
                const char* bp = bufB + (warpN * 32 + j * 8 + g) * APITCH_B +
                                 (kk + 2 * t4) * 2;
                bh[j][0] = *(const uint32_t*)(bp);
                bh[j][1] = *(const uint32_t*)(bp + 16);
                bm[j][0] = *(const uint32_t*)(bp + ARR_B);
                bm[j][1] = *(const uint32_t*)(bp + ARR_B + 16);
            }
            #pragma unroll
            for (int i = 0; i < 4; i++) {
                const char* ap = bufA + (warpM * 64 + i * 16 + g) * APITCH_B +
                                 (kk + 2 * t4) * 2;
                uint32_t ah0 = *(const uint32_t*)(ap);
                uint32_t ah1 = *(const uint32_t*)(ap + 8 * APITCH_B);
                uint32_t ah2 = *(const uint32_t*)(ap + 16);
                uint32_t ah3 = *(const uint32_t*)(ap + 8 * APITCH_B + 16);
                uint32_t am0 = *(const uint32_t*)(ap + ARR_B);
                uint32_t am1 = *(const uint32_t*)(ap + ARR_B + 8 * APITCH_B);
                uint32_t am2 = *(const uint32_t*)(ap + ARR_B + 16);
                uint32_t am3 = *(const uint32_t*)(ap + ARR_B + 8 * APITCH_B + 16);
                #pragma unroll
                for (int j = 0; j < 4; j++) {
                    MMA_F32ACC(acc[i][j], ah0, ah1, ah2, ah3, bh[j][0], bh[j][1]);
                    MMA_F16ACC(acc16[i][j], am0, am1, am2, am3, bh[j][0], bh[j][1]);
                    MMA_F16ACC(acc16[i][j], ah0, ah1, ah2, ah3, bm[j][0], bm[j][1]);
                }
            }
        }
        __syncthreads();
    }

    // epilogue: main + corrections + bias, relu, fp32 out (row stride HH)
    #pragma unroll
    for (int j = 0; j < 4; j++) {
        int col = nBase + warpN * 32 + j * 8 + 2 * t4;
        float bv0 = __ldg(&bias[col]), bv1 = __ldg(&bias[col + 1]);
        #pragma unroll
        for (int i = 0; i < 4; i++) {
            __half2 c01 = *(__half2*)&acc16[i][j][0];
            __half2 c23 = *(__half2*)&acc16[i][j][1];
            float2 f01 = __half22float2(c01);
            float2 f23 = __half22float2(c23);
            int r0 = mBase + warpM * 64 + i * 16 + g;
            if (r0 < M) {
                float2 v0 = make_float2(
                    fmaxf(acc[i][j][0] + f01.x + bv0, 0.f),
                    fmaxf(acc[i][j][1] + f01.y + bv1, 0.f));
                *(float2*)(Xout + (size_t)r0 * HH + col) = v0;
            }
            int r1 = r0 + 8;
            if (r1 < M) {
                float2 v1 = make_float2(
                    fmaxf(acc[i][j][2] + f23.x + bv0, 0.f),
                    fmaxf(acc[i][j][3] + f23.y + bv1, 0.f));
                *(float2*)(Xout + (size_t)r1 * HH + col) = v1;
            }
        }
    }
}

// ---------------- final small GEMM: S[N,3] = X[N,512] @ W1[512,3] ----------------
__global__ void gemm_small_kernel(const float* __restrict__ X,
                                  const float* __restrict__ W1,
                                  float* __restrict__ S) {
    int row = blockIdx.x * (blockDim.x / 32) + (threadIdx.x >> 5);
    int lane = threadIdx.x & 31;
    if (row >= NN) return;
    float a0 = 0.f, a1 = 0.f, a2 = 0.f;
    const float* xr = X + (size_t)row * HH;
    for (int k = lane; k < HH; k += 32) {
        float xv = xr[k];
        a0 += xv * W1[k * 3 + 0];
        a1 += xv * W1[k * 3 + 1];
        a2 += xv * W1[k * 3 + 2];
    }
    #pragma unroll
    for (int off = 16; off; off >>= 1) {
        a0 += __shfl_down_sync(0xffffffffu, a0, off);
        a1 += __shfl_down_sync(0xffffffffu, a1, off);
        a2 += __shfl_down_sync(0xffffffffu, a2, off);
    }
    if (lane == 0) {
        S[row * 3 + 0] = a0;
        S[row * 3 + 1] = a1;
        S[row * 3 + 2] = a2;
    }
}

__global__ void agg_final_kernel(const float* __restrict__ S,
                                 const float* __restrict__ b1,
                                 float* __restrict__ out) {
    int i = blockIdx.x * blockDim.x + threadIdx.x;
    if (i >= NN) return;
    float a0 = 0.f, a1 = 0.f, a2 = 0.f;
    int beg = g_rowptr[i], end = g_rowptr[i + 1];
    for (int e = beg; e < end; e++) {
        int s = g_col[e];
        float cf = g_coef[e];
        a0 += cf * S[s * 3 + 0];
        a1 += cf * S[s * 3 + 1];
        a2 += cf * S[s * 3 + 2];
    }
    out[i * 3 + 0] = a0 + b1[0];
    out[i * 3 + 1] = a1 + b1[1];
    out[i * 3 + 2] = a2 + b1[2];
}

// ---------------- host orchestration ----------------
extern "C" void kernel_launch(void* const* d_in, const int* in_sizes, int n_in,
                              void* d_out, int out_size) {
    const float* x  = (const float*)d_in[0];
    const void*  ei = d_in[1];
    const float* W0 = (const float*)d_in[2];
    const float* b0 = (const float*)d_in[3];
    const float* Wr = (const float*)d_in[4];
    const float* br = (const float*)d_in[5];
    const float* W1 = (const float*)d_in[6];
    const float* b1 = (const float*)d_in[7];
    float* out  = (float*)d_out;
    float* outX = out + (size_t)NN * CC;

    float *gX, *gS;
    __half *gAh, *gAm, *gWh, *gWm;
    int *gCnt, *gFill;
    unsigned* gIs32;
    cudaGetSymbolAddress((void**)&gX,  g_X);
    cudaGetSymbolAddress((void**)&gS,  g_S);
    cudaGetSymbolAddress((void**)&gAh, g_Ah);
    cudaGetSymbolAddress((void**)&gAm, g_Am);
    cudaGetSymbolAddress((void**)&gWh, g_Wh);
    cudaGetSymbolAddress((void**)&gWm, g_Wm);
    cudaGetSymbolAddress((void**)&gCnt, g_cnt);
    cudaGetSymbolAddress((void**)&gFill, g_fill);
    cudaGetSymbolAddress((void**)&gIs32, g_is32);

    cudaFuncSetAttribute(gemm_mma_kernel,
                         cudaFuncAttributeMaxDynamicSharedMemorySize, GSMEM_B);

    // preprocessing: CSR (with self-loops) + normalization + weight split
    cudaMemsetAsync(gCnt, 0, NN * sizeof(int));
    cudaMemsetAsync(gFill, 0, NN * sizeof(int));
    cudaMemsetAsync(gIs32, 0, sizeof(unsigned));
    detect_kernel<<<256, 256>>>((const unsigned*)ei);
    convert_count_kernel<<<(EE + 255) / 256, 256>>>(ei);
    scan_kernel<<<1, 1024>>>();
    fill_kernel<<<(EE + 255) / 256, 256>>>();
    wsplit_kernel<<<dim3(HH, 13), 256>>>(W0, Wr);

    dim3 gg(NPAD / 128, 4);

    // layer 0: agg on F=256 (split output), then HMMA GEMM K=256
    agg_kernel<FF / 4><<<NN, FF / 4>>>(x, gAh, gAm, FF);
    gemm_mma_kernel<<<gg, 256, GSMEM_B>>>(gAh, gAm, gWh, gWm, b0, gX,
                                          NN, FF, FF);

    // 12 residual-block convs: relu(A x W + b)
    for (int L = 1; L <= 12; L++) {
        agg_kernel<HH / 4><<<NN, HH / 4>>>(gX, gAh, gAm, HH);
        float* dst = (L == 12) ? outX : gX;
        gemm_mma_kernel<<<gg, 256, GSMEM_B>>>(
            gAh, gAm,
            gWh + (size_t)L * HH * HH, gWm + (size_t)L * HH * HH,
            br + (size_t)(L - 1) * HH, dst, NN, HH, HH);
    }

    // final conv: GEMM first (H->3), then aggregate on 3 cols + bias
    gemm_small_kernel<<<(NN + 7) / 8, 256>>>(outX, W1, gS);
    agg_final_kernel<<<(NN + 255) / 256, 256>>>(gS, b1, out);
}

// round 6
// speedup vs baseline: 1.0817x; 1.0817x over previous
#include <cuda_runtime.h>
#include <cuda_bf16.h>
#include <cstdint>

#define NN 50000
#define EE 400000
#define FF 256
#define HH 512
#define CC 3
#define NPAD 50048              // 391 * 128

// ---------------- device scratch ----------------
__device__ float g_X[(size_t)NPAD * HH];          // fp32 activations
__device__ __nv_bfloat16 g_Ah[(size_t)NPAD * HH]; // agg output hi
__device__ __nv_bfloat16 g_Am[(size_t)NPAD * HH]; // agg output mid
__device__ __nv_bfloat16 g_Wh[(size_t)13 * HH * HH];  // transposed [n][k]
__device__ __nv_bfloat16 g_Wm[(size_t)13 * HH * HH];
__device__ float g_S[(size_t)NN * CC];
__device__ float g_dinv[NN];
__device__ float g_coef[EE + NN];   // CSR coefs incl. self loops
__device__ int   g_col[EE + NN];
__device__ int   g_srcA[EE];
__device__ int   g_dstA[EE];
__device__ int   g_cnt[NN];
__device__ int   g_fill[NN];
__device__ int   g_rowptr[NN + 1];
__device__ unsigned g_is32;

// ---------------- preprocessing ----------------
__global__ void detect_kernel(const unsigned* __restrict__ w) {
    unsigned local = 0;
    for (int i = blockIdx.x * blockDim.x + threadIdx.x; i < EE;
         i += gridDim.x * blockDim.x)
        local |= w[2 * i + 1];
    #pragma unroll
    for (int off = 16; off; off >>= 1)
        local |= __shfl_xor_sync(0xffffffffu, local, off);
    if ((threadIdx.x & 31) == 0 && local) atomicOr(&g_is32, 1u);
}

__global__ void convert_count_kernel(const void* __restrict__ ei) {
    int e = blockIdx.x * blockDim.x + threadIdx.x;
    if (e >= EE) return;
    int s, d;
    if (g_is32) {
        const int* p = (const int*)ei;
        s = p[e]; d = p[EE + e];
    } else {
        const long long* p = (const long long*)ei;
        s = (int)p[e]; d = (int)p[EE + e];
    }
    g_srcA[e] = s; g_dstA[e] = d;
    atomicAdd(&g_cnt[d], 1);
}

// single block: exclusive scan of (cnt+1), dinv, self-loop CSR entries
__global__ void scan_kernel() {
    __shared__ int s[1024];
    const int T = 1024;
    int tid = threadIdx.x;
    int chunk = (NN + T - 1) / T;
    int beg = tid * chunk;
    int end = min(beg + chunk, NN);
    int sum = 0;
    for (int i = beg; i < end; i++) sum += g_cnt[i] + 1;
    s[tid] = sum;
    __syncthreads();
    for (int off = 1; off < T; off <<= 1) {
        int v = (tid >= off) ? s[tid - off] : 0;
        __syncthreads();
        s[tid] += v;
        __syncthreads();
    }
    int run = (tid > 0) ? s[tid - 1] : 0;
    for (int i = beg; i < end; i++) {
        int c = g_cnt[i];
        float di = rsqrtf((float)c + 1.0f);
        g_rowptr[i] = run;
        g_dinv[i] = di;
        g_col[run + c] = i;          // self-loop in last slot
        g_coef[run + c] = di * di;
        run += c + 1;
    }
    if (tid == T - 1) g_rowptr[NN] = run;
}

__global__ void fill_kernel() {
    int e = blockIdx.x * blockDim.x + threadIdx.x;
    if (e >= EE) return;
    int d = g_dstA[e], s = g_srcA[e];
    int pos = g_rowptr[d] + atomicAdd(&g_fill[d], 1);
    g_col[pos]  = s;
    g_coef[pos] = g_dinv[s] * g_dinv[d];
}

// ---------------- weight transpose + bf16 hi/mid split ----------------
__global__ void wsplit_kernel(const float* __restrict__ W0,
                              const float* __restrict__ Wr) {
    int L = blockIdx.y;
    int n = blockIdx.x;
    int K = (L == 0) ? FF : HH;
    const float* W = (L == 0) ? W0 : (Wr + (size_t)(L - 1) * HH * HH);
    size_t slot = (size_t)L * HH * HH;
    for (int k = threadIdx.x; k < K; k += blockDim.x) {
        float x = W[(size_t)k * HH + n];
        __nv_bfloat16 h = __float2bfloat16_rn(x);
        float r = x - __bfloat162float(h);
        g_Wh[slot + (size_t)n * K + k] = h;
        g_Wm[slot + (size_t)n * K + k] = __float2bfloat16_rn(r);
    }
}

// ---------------- aggregation: bf16 hi/mid split output ----------------
template <int W4>
__global__ void agg_kernel(const float* __restrict__ X,
                           __nv_bfloat16* __restrict__ Th,
                           __nv_bfloat16* __restrict__ Tm, int sA) {
    int node = blockIdx.x;
    int t = threadIdx.x;
    const float4* Xv = (const float4*)X;
    float4 acc = make_float4(0.f, 0.f, 0.f, 0.f);
    int beg = g_rowptr[node], end = g_rowptr[node + 1];
    for (int e = beg; e < end; e++) {
        int s = g_col[e];
        float cf = g_coef[e];
        float4 v = Xv[(size_t)s * W4 + t];
        acc.x += cf * v.x; acc.y += cf * v.y;
        acc.z += cf * v.z; acc.w += cf * v.w;
    }
    float vals[4] = {acc.x, acc.y, acc.z, acc.w};
    unsigned hb[4], mb[4];
    #pragma unroll
    for (int i = 0; i < 4; i++) {
        __nv_bfloat16 h = __float2bfloat16_rn(vals[i]);
        float r = vals[i] - __bfloat162float(h);
        __nv_bfloat16 m = __float2bfloat16_rn(r);
        hb[i] = (unsigned)__bfloat16_as_ushort(h);
        mb[i] = (unsigned)__bfloat16_as_ushort(m);
    }
    uint2 ph, pm;
    ph.x = hb[0] | (hb[1] << 16); ph.y = hb[2] | (hb[3] << 16);
    pm.x = mb[0] | (mb[1] << 16); pm.y = mb[2] | (mb[3] << 16);
    size_t off = (size_t)node * sA + 4 * t;
    *(uint2*)(Th + off) = ph;
    *(uint2*)(Tm + off) = pm;
}

// ---------------- persistent HMMA bf16x3 GEMM ----------------
// C[M,512] = relu(A[M,K] @ W[K,512] + bias)
// Block tile 128x128, 8 warps (2M x 4N), BK=32, 2-stage cp.async,
// persistent CTAs with cross-tile pipelining; ldmatrix fragment loads.
#define APITCH_B 80          // bytes per smem row
#define ARR_B    10240       // bytes per array (128*80)
#define STAGE_B  40960       // 4 arrays
#define GSMEM_B  81920       // 2 stages

#define MMA_B16(cc, A0, A1, A2, A3, B0, B1)                                   \
    asm volatile(                                                             \
        "mma.sync.aligned.m16n8k16.row.col.f32.bf16.bf16.f32 "                \
        "{%0,%1,%2,%3}, {%4,%5,%6,%7}, {%8,%9}, {%0,%1,%2,%3};"               \
        : "+f"(cc[0]), "+f"(cc[1]), "+f"(cc[2]), "+f"(cc[3])                  \
        : "r"(A0), "r"(A1), "r"(A2), "r"(A3), "r"(B0), "r"(B1))

#define LDSM4(r0, r1, r2, r3, addr)                                           \
    asm volatile("ldmatrix.sync.aligned.m8n8.x4.shared.b16 {%0,%1,%2,%3}, [%4];" \
        : "=r"(r0), "=r"(r1), "=r"(r2), "=r"(r3) : "r"(addr))

__global__ void __launch_bounds__(256, 2) gemm_mma_kernel(
    const __nv_bfloat16* __restrict__ Ah, const __nv_bfloat16* __restrict__ Am,
    const __nv_bfloat16* __restrict__ Wh, const __nv_bfloat16* __restrict__ Wm,
    const float* __restrict__ bias, float* __restrict__ Xout,
    int M, int K, int sA, int nTiles, int kshift) {
    extern __shared__ char smb[];
    uint32_t sbase;
    asm("{ .reg .u64 t; cvta.to.shared.u64 t, %1; cvt.u32.u64 %0, t; }"
        : "=r"(sbase) : "l"(smb));

    const int tid = threadIdx.x;
    const int lane = tid & 31, wid = tid >> 5;
    const int g = lane >> 2, t4 = lane & 3;
    const int warpM = wid & 1, warpN = wid >> 1;
    const int kmask = (1 << kshift) - 1;

    // my tile count -> slot count
    const int myTiles = (nTiles - blockIdx.x + gridDim.x - 1) / gridDim.x;
    const int totalSlots = myTiles << kshift;

    // ldmatrix lane geometry
    const int aLRow = (lane & 7) + ((lane >> 3) & 1) * 8;
    const int aLCol = ((lane >> 4) & 1) * 8;
    const int bLRow = (lane & 7) + ((lane >> 4) & 1) * 8;
    const int bLCol = ((lane >> 3) & 1) * 8;
    const uint32_t aAddr0 = sbase + (warpM * 64 + aLRow) * APITCH_B + aLCol * 2;
    const uint32_t bAddr0 = sbase + 2 * ARR_B + (warpN * 32 + bLRow) * APITCH_B + bLCol * 2;

    // staging geometry
    const int sRow = tid >> 1;                  // handled via q loop below
    (void)sRow;

    float acc[4][4][4];
    #pragma unroll
    for (int i = 0; i < 4; i++)
        #pragma unroll
        for (int j = 0; j < 4; j++)
            #pragma unroll
            for (int v = 0; v < 4; v++) acc[i][j][v] = 0.f;

    #define DECODE(s, cc, mB, nB) do {                                         \
        int tI_ = (s) >> kshift;                                               \
        int tile_ = blockIdx.x + tI_ * gridDim.x;                              \
        cc = (s) & kmask;                                                      \
        nB = (tile_ & 3) << 7;                                                 \
        mB = (tile_ >> 2) << 7;                                                \
    } while (0)

    #define STAGE_LOAD(buf, cc, mB, nB) do {                                   \
        int k0 = (cc) * 32;                                                    \
        uint32_t sb = sbase + (buf) * STAGE_B;                                 \
        _Pragma("unroll")                                                      \
        for (int h = 0; h < 2; h++) {                                          \
            int q = tid + h * 256;                                             \
            int row = q >> 2, c16 = q & 3;                                     \
            uint32_t ds = sb + row * APITCH_B + c16 * 16;                      \
            long long aoff = (long long)((mB) + row) * sA + k0 + c16 * 8;      \
            asm volatile("cp.async.cg.shared.global [%0], [%1], 16;"           \
                :: "r"(ds), "l"(Ah + aoff));                                   \
            asm volatile("cp.async.cg.shared.global [%0], [%1], 16;"           \
                :: "r"(ds + ARR_B), "l"(Am + aoff));                           \
            long long boff = (long long)((nB) + row) * K + k0 + c16 * 8;       \
            asm volatile("cp.async.cg.shared.global [%0], [%1], 16;"           \
                :: "r"(ds + 2 * ARR_B), "l"(Wh + boff));                       \
            asm volatile("cp.async.cg.shared.global [%0], [%1], 16;"           \
                :: "r"(ds + 3 * ARR_B), "l"(Wm + boff));                       \
        }                                                                      \
        asm volatile("cp.async.commit_group;");                                \
    } while (0)

    {
        int c0, mB0, nB0;
        DECODE(0, c0, mB0, nB0);
        STAGE_LOAD(0, c0, mB0, nB0);
    }

    for (int s = 0; s < totalSlots; s++) {
        if (s + 1 < totalSlots) {
            int cN, mBN, nBN;
            DECODE(s + 1, cN, mBN, nBN);
            STAGE_LOAD((s + 1) & 1, cN, mBN, nBN);
            asm volatile("cp.async.wait_group 1;");
        } else {
            asm volatile("cp.async.wait_group 0;");
        }
        __syncthreads();

        const uint32_t stOff = (s & 1) * STAGE_B;
        #pragma unroll
        for (int kk = 0; kk < 32; kk += 16) {
            uint32_t bh[4][2], bm[4][2];
            #pragma unroll
            for (int jp = 0; jp < 2; jp++) {
                uint32_t ba = bAddr0 + stOff + jp * (16 * APITCH_B) + kk * 2;
                LDSM4(bh[2 * jp][0], bh[2 * jp][1],
                      bh[2 * jp + 1][0], bh[2 * jp + 1][1], ba);
                LDSM4(bm[2 * jp][0], bm[2 * jp][1],
                      bm[2 * jp + 1][0], bm[2 * jp + 1][1], ba + ARR_B);
            }
            #pragma unroll
            for (int i = 0; i < 4; i++) {
                uint32_t aa = aAddr0 + stOff + i * (16 * APITCH_B) + kk * 2;
                uint32_t ah0, ah1, ah2, ah3, am0, am1, am2, am3;
                LDSM4(ah0, ah1, ah2, ah3, aa);
                LDSM4(am0, am1, am2, am3, aa + ARR_B);
                #pragma unroll
                for (int j = 0; j < 4; j++) {
                    MMA_B16(acc[i][j], ah0, ah1, ah2, ah3, bh[j][0], bh[j][1]);
                    MMA_B16(acc[i][j], am0, am1, am2, am3, bh[j][0], bh[j][1]);
                    MMA_B16(acc[i][j], ah0, ah1, ah2, ah3, bm[j][0], bm[j][1]);
                }
            }
        }

        if ((s & kmask) == kmask) {
            // epilogue for this tile (regs only -> gmem; overlaps with in-flight cp.async)
            int cE, mB, nB;
            DECODE(s, cE, mB, nB);
            #pragma unroll
            for (int j = 0; j < 4; j++) {
                int col = nB + warpN * 32 + j * 8 + 2 * t4;
                float bv0 = __ldg(&bias[col]), bv1 = __ldg(&bias[col + 1]);
                #pragma unroll
                for (int i = 0; i < 4; i++) {
                    int r0 = mB + warpM * 64 + i * 16 + g;
                    if (r0 < M) {
                        float2 v0 = make_float2(fmaxf(acc[i][j][0] + bv0, 0.f),
                                                fmaxf(acc[i][j][1] + bv1, 0.f));
                        *(float2*)(Xout + (size_t)r0 * HH + col) = v0;
                    }
                    int r1 = r0 + 8;
                    if (r1 < M) {
                        float2 v1 = make_float2(fmaxf(acc[i][j][2] + bv0, 0.f),
                                                fmaxf(acc[i][j][3] + bv1, 0.f));
                        *(float2*)(Xout + (size_t)r1 * HH + col) = v1;
                    }
                    #pragma unroll
                    for (int v = 0; v < 4; v++) acc[i][j][v] = 0.f;
                }
            }
        }
        __syncthreads();
    }
}

// ---------------- final small GEMM: S[N,3] = X[N,512] @ W1[512,3] ----------------
__global__ void gemm_small_kernel(const float* __restrict__ X,
                                  const float* __restrict__ W1,
                                  float* __restrict__ S) {
    int row = blockIdx.x * (blockDim.x / 32) + (threadIdx.x >> 5);
    int lane = threadIdx.x & 31;
    if (row >= NN) return;
    float a0 = 0.f, a1 = 0.f, a2 = 0.f;
    const float* xr = X + (size_t)row * HH;
    for (int k = lane; k < HH; k += 32) {
        float xv = xr[k];
        a0 += xv * W1[k * 3 + 0];
        a1 += xv * W1[k * 3 + 1];
        a2 += xv * W1[k * 3 + 2];
    }
    #pragma unroll
    for (int off = 16; off; off >>= 1) {
        a0 += __shfl_down_sync(0xffffffffu, a0, off);
        a1 += __shfl_down_sync(0xffffffffu, a1, off);
        a2 += __shfl_down_sync(0xffffffffu, a2, off);
    }
    if (lane == 0) {
        S[row * 3 + 0] = a0;
        S[row * 3 + 1] = a1;
        S[row * 3 + 2] = a2;
    }
}

__global__ void agg_final_kernel(const float* __restrict__ S,
                                 const float* __restrict__ b1,
                                 float* __restrict__ out) {
    int i = blockIdx.x * blockDim.x + threadIdx.x;
    if (i >= NN) return;
    float a0 = 0.f, a1 = 0.f, a2 = 0.f;
    int beg = g_rowptr[i], end = g_rowptr[i + 1];
    for (int e = beg; e < end; e++) {
        int s = g_col[e];
        float cf = g_coef[e];
        a0 += cf * S[s * 3 + 0];
        a1 += cf * S[s * 3 + 1];
        a2 += cf * S[s * 3 + 2];
    }
    out[i * 3 + 0] = a0 + b1[0];
    out[i * 3 + 1] = a1 + b1[1];
    out[i * 3 + 2] = a2 + b1[2];
}

// ---------------- host orchestration ----------------
extern "C" void kernel_launch(void* const* d_in, const int* in_sizes, int n_in,
                              void* d_out, int out_size) {
    const float* x  = (const float*)d_in[0];
    const void*  ei = d_in[1];
    const float* W0 = (const float*)d_in[2];
    const float* b0 = (const float*)d_in[3];
    const float* Wr = (const float*)d_in[4];
    const float* br = (const float*)d_in[5];
    const float* W1 = (const float*)d_in[6];
    const float* b1 = (const float*)d_in[7];
    float* out  = (float*)d_out;
    float* outX = out + (size_t)NN * CC;

    float *gX, *gS;
    __nv_bfloat16 *gAh, *gAm, *gWh, *gWm;
    int *gCnt, *gFill;
    unsigned* gIs32;
    cudaGetSymbolAddress((void**)&gX,  g_X);
    cudaGetSymbolAddress((void**)&gS,  g_S);
    cudaGetSymbolAddress((void**)&gAh, g_Ah);
    cudaGetSymbolAddress((void**)&gAm, g_Am);
    cudaGetSymbolAddress((void**)&gWh, g_Wh);
    cudaGetSymbolAddress((void**)&gWm, g_Wm);
    cudaGetSymbolAddress((void**)&gCnt, g_cnt);
    cudaGetSymbolAddress((void**)&gFill, g_fill);
    cudaGetSymbolAddress((void**)&gIs32, g_is32);

    cudaFuncSetAttribute(gemm_mma_kernel,
                         cudaFuncAttributeMaxDynamicSharedMemorySize, GSMEM_B);

    // preprocessing: CSR (with self-loops) + normalization + weight split
    cudaMemsetAsync(gCnt, 0, NN * sizeof(int));
    cudaMemsetAsync(gFill, 0, NN * sizeof(int));
    cudaMemsetAsync(gIs32, 0, sizeof(unsigned));
    detect_kernel<<<256, 256>>>((const unsigned*)ei);
    convert_count_kernel<<<(EE + 255) / 256, 256>>>(ei);
    scan_kernel<<<1, 1024>>>();
    fill_kernel<<<(EE + 255) / 256, 256>>>();
    wsplit_kernel<<<dim3(HH, 13), 256>>>(W0, Wr);

    const int nTiles = (NPAD / 128) * 4;   // 1564
    const int gGrid = 296;                 // 2 CTAs per SM

    // layer 0: agg on F=256 (split output), then persistent HMMA GEMM K=256
    agg_kernel<FF / 4><<<NN, FF / 4>>>(x, gAh, gAm, FF);
    gemm_mma_kernel<<<gGrid, 256, GSMEM_B>>>(gAh, gAm, gWh, gWm, b0, gX,
                                             NN, FF, FF, nTiles, 3);

    // 12 residual-block convs: relu(A x W + b)
    for (int L = 1; L <= 12; L++) {
        agg_kernel<HH / 4><<<NN, HH / 4>>>(gX, gAh, gAm, HH);
        float* dst = (L == 12) ? outX : gX;
        gemm_mma_kernel<<<gGrid, 256, GSMEM_B>>>(
            gAh, gAm,
            gWh + (size_t)L * HH * HH, gWm + (size_t)L * HH * HH,
            br + (size_t)(L - 1) * HH, dst, NN, HH, HH, nTiles, 4);
    }

    // final conv: GEMM first (H->3), then aggregate on 3 cols + bias
    gemm_small_kernel<<<(NN + 7) / 8, 256>>>(outX, W1, gS);
    agg_final_kernel<<<(NN + 255) / 256, 256>>>(gS, b1, out);
}

// round 7
// speedup vs baseline: 1.2675x; 1.1717x over previous
#include <cuda_runtime.h>
#include <cuda_bf16.h>
#include <cstdint>

#define NN 50000
#define EE 400000
#define FF 256
#define HH 512
#define CC 3
#define NPAD 50048                        // 391 * 128
#define CHA ((size_t)NPAD * 128)          // A chunk stride (bytes)
#define WCH ((size_t)512 * 128)           // W chunk stride (bytes)
#define WSLOT ((size_t)16 * 512 * 128)    // W layer slot stride (bytes)

// ---------------- device scratch ----------------
__device__ float g_X[(size_t)NPAD * HH];            // fp32 activations
__device__ unsigned char g_A[(size_t)16 * NPAD * 128];   // blocked bf16 hi|mid, swizzled
__device__ unsigned char g_W[(size_t)13 * 16 * 512 * 128];
__device__ float g_S[(size_t)NN * CC];
__device__ float g_dinv[NN];
__device__ float g_coef[EE + NN];
__device__ int   g_col[EE + NN];
__device__ int   g_srcA[EE];
__device__ int   g_dstA[EE];
__device__ int   g_cnt[NN];
__device__ int   g_fill[NN];
__device__ int   g_rowptr[NN + 1];
__device__ unsigned g_is32;

// ---------------- preprocessing ----------------
__global__ void detect_kernel(const unsigned* __restrict__ w) {
    unsigned local = 0;
    for (int i = blockIdx.x * blockDim.x + threadIdx.x; i < EE;
         i += gridDim.x * blockDim.x)
        local |= w[2 * i + 1];
    #pragma unroll
    for (int off = 16; off; off >>= 1)
        local |= __shfl_xor_sync(0xffffffffu, local, off);
    if ((threadIdx.x & 31) == 0 && local) atomicOr(&g_is32, 1u);
}

__global__ void convert_count_kernel(const void* __restrict__ ei) {
    int e = blockIdx.x * blockDim.x + threadIdx.x;
    if (e >= EE) return;
    int s, d;
    if (g_is32) {
        const int* p = (const int*)ei;
        s = p[e]; d = p[EE + e];
    } else {
        const long long* p = (const long long*)ei;
        s = (int)p[e]; d = (int)p[EE + e];
    }
    g_srcA[e] = s; g_dstA[e] = d;
    atomicAdd(&g_cnt[d], 1);
}

__global__ void scan_kernel() {
    __shared__ int s[1024];
    const int T = 1024;
    int tid = threadIdx.x;
    int chunk = (NN + T - 1) / T;
    int beg = tid * chunk;
    int end = min(beg + chunk, NN);
    int sum = 0;
    for (int i = beg; i < end; i++) sum += g_cnt[i] + 1;
    s[tid] = sum;
    __syncthreads();
    for (int off = 1; off < T; off <<= 1) {
        int v = (tid >= off) ? s[tid - off] : 0;
        __syncthreads();
        s[tid] += v;
        __syncthreads();
    }
    int run = (tid > 0) ? s[tid - 1] : 0;
    for (int i = beg; i < end; i++) {
        int c = g_cnt[i];
        float di = rsqrtf((float)c + 1.0f);
        g_rowptr[i] = run;
        g_dinv[i] = di;
        g_col[run + c] = i;
        g_coef[run + c] = di * di;
        run += c + 1;
    }
    if (tid == T - 1) g_rowptr[NN] = run;
}

__global__ void fill_kernel() {
    int e = blockIdx.x * blockDim.x + threadIdx.x;
    if (e >= EE) return;
    int d = g_dstA[e], s = g_srcA[e];
    int pos = g_rowptr[d] + atomicAdd(&g_fill[d], 1);
    g_col[pos]  = s;
    g_coef[pos] = g_dinv[s] * g_dinv[d];
}

// ---------------- weight split into blocked swizzled layout ----------------
// dst block for (L, kc, n): 128 bytes = hi 4x16B | mid 4x16B, phys16 = b ^ (n&7)
__global__ void wsplit_kernel(const float* __restrict__ W0,
                              const float* __restrict__ Wr) {
    int L = blockIdx.y;
    int n = blockIdx.x;
    int K = (L == 0) ? FF : HH;
    const float* W = (L == 0) ? W0 : (Wr + (size_t)(L - 1) * HH * HH);
    unsigned char* slot = g_W + (size_t)L * WSLOT;
    int t = threadIdx.x;
    if (t >= (K >> 3)) return;
    int kc = t >> 2, c16 = t & 3, k0 = t * 8;
    unsigned hw[4], mw[4];
    #pragma unroll
    for (int p = 0; p < 4; p++) {
        unsigned hlo, hhi, mlo, mhi;
        {
            float x = W[(size_t)(k0 + 2 * p) * HH + n];
            __nv_bfloat16 h = __float2bfloat16_rn(x);
            float r = x - __bfloat162float(h);
            hlo = (unsigned)__bfloat16_as_ushort(h);
            mlo = (unsigned)__bfloat16_as_ushort(__float2bfloat16_rn(r));
        }
        {
            float x = W[(size_t)(k0 + 2 * p + 1) * HH + n];
            __nv_bfloat16 h = __float2bfloat16_rn(x);
            float r = x - __bfloat162float(h);
            hhi = (unsigned)__bfloat16_as_ushort(h);
            mhi = (unsigned)__bfloat16_as_ushort(__float2bfloat16_rn(r));
        }
        hw[p] = hlo | (hhi << 16);
        mw[p] = mlo | (mhi << 16);
    }
    unsigned char* base = slot + (size_t)kc * WCH + (size_t)n * 128;
    uint32_t physHi = ((uint32_t)(c16 ^ (n & 7))) << 4;
    *(uint4*)(base + physHi) = make_uint4(hw[0], hw[1], hw[2], hw[3]);
    *(uint4*)(base + (physHi ^ 64)) = make_uint4(mw[0], mw[1], mw[2], mw[3]);
}

// ---------------- aggregation -> blocked swizzled bf16 hi|mid ----------------
template <int W4>
__global__ void agg_kernel(const float* __restrict__ X,
                           unsigned char* __restrict__ gA) {
    int node = blockIdx.x;
    int t = threadIdx.x;
    const float4* Xv = (const float4*)X;
    float4 acc = make_float4(0.f, 0.f, 0.f, 0.f);
    int beg = g_rowptr[node], end = g_rowptr[node + 1];
    for (int e = beg; e < end; e++) {
        int s = g_col[e];
        float cf = g_coef[e];
        float4 v = Xv[(size_t)s * W4 + t];
        acc.x += cf * v.x; acc.y += cf * v.y;
        acc.z += cf * v.z; acc.w += cf * v.w;
    }
    float vals[4] = {acc.x, acc.y, acc.z, acc.w};
    unsigned hb[4], mb[4];
    #pragma unroll
    for (int i = 0; i < 4; i++) {
        __nv_bfloat16 h = __float2bfloat16_rn(vals[i]);
        float r = vals[i] - __bfloat162float(h);
        __nv_bfloat16 m = __float2bfloat16_rn(r);
        hb[i] = (unsigned)__bfloat16_as_ushort(h);
        mb[i] = (unsigned)__bfloat16_as_ushort(m);
    }
    uint2 ph, pm;
    ph.x = hb[0] | (hb[1] << 16); ph.y = hb[2] | (hb[3] << 16);
    pm.x = mb[0] | (mb[1] << 16); pm.y = mb[2] | (mb[3] << 16);
    int kc = t >> 3, c16 = (t >> 1) & 3, half = (t & 1) * 8;
    unsigned char* base = gA + (size_t)kc * CHA + (size_t)node * 128;
    uint32_t physHi = ((uint32_t)(c16 ^ (node & 7))) << 4;
    *(uint2*)(base + physHi + half) = ph;
    *(uint2*)(base + (physHi ^ 64) + half) = pm;
}

// ---------------- persistent HMMA bf16x3 GEMM with TMA bulk staging ----------
// Block tile 128x128, 8 warps, BK=32. Stage = A 16KB + B 16KB; 2 stages + mbarriers.
#define STG_B   32768
#define SMEM_REQ (1024 + 128 + 2 * STG_B)

#define MMA_B16(cc, A0, A1, A2, A3, B0, B1)                                   \
    asm volatile(                                                             \
        "mma.sync.aligned.m16n8k16.row.col.f32.bf16.bf16.f32 "                \
        "{%0,%1,%2,%3}, {%4,%5,%6,%7}, {%8,%9}, {%0,%1,%2,%3};"               \
        : "+f"(cc[0]), "+f"(cc[1]), "+f"(cc[2]), "+f"(cc[3])                  \
        : "r"(A0), "r"(A1), "r"(A2), "r"(A3), "r"(B0), "r"(B1))

#define LDSM4(r0, r1, r2, r3, addr)                                           \
    asm volatile("ldmatrix.sync.aligned.m8n8.x4.shared.b16 {%0,%1,%2,%3}, [%4];" \
        : "=r"(r0), "=r"(r1), "=r"(r2), "=r"(r3) : "r"(addr))

__device__ __forceinline__ void mbar_wait(uint32_t mb, uint32_t parity) {
    uint32_t done;
    asm volatile("{\n\t.reg .pred p;\n\t"
                 "mbarrier.try_wait.parity.shared.b64 p, [%1], %2;\n\t"
                 "selp.b32 %0, 1, 0, p;\n\t}"
                 : "=r"(done) : "r"(mb), "r"(parity) : "memory");
    if (!done) {
        asm volatile("{\n\t.reg .pred P1;\n\t"
                     "WL_%=:\n\t"
                     "mbarrier.try_wait.parity.shared.b64 P1, [%0], %1;\n\t"
                     "@P1 bra.uni WD_%=;\n\t"
                     "bra.uni WL_%=;\n\t"
                     "WD_%=:\n\t}" :: "r"(mb), "r"(parity) : "memory");
    }
}

__global__ void __launch_bounds__(256, 2) gemm_mma_kernel(
    const unsigned char* __restrict__ gA,
    const unsigned char* __restrict__ gW,
    const float* __restrict__ bias, float* __restrict__ Xout,
    int M, int nTiles, int kshift) {
    extern __shared__ char smb[];
    uint32_t sraw;
    asm("{ .reg .u64 t; cvta.to.shared.u64 t, %1; cvt.u32.u64 %0, t; }"
        : "=r"(sraw) : "l"(smb));
    const uint32_t sb = (sraw + 1023) & ~1023u;
    const uint32_t bufBase = sb + 128;

    const int tid = threadIdx.x;
    const int lane = tid & 31, wid = tid >> 5;
    const int g = lane >> 2, t4 = lane & 3;
    const int warpM = wid & 1, warpN = wid >> 1;
    const int kmask = (1 << kshift) - 1;
    const int myTiles = (nTiles - blockIdx.x + gridDim.x - 1) / gridDim.x;
    const int totalSlots = myTiles << kshift;

    // fragment geometry (swizzled 128B rows)
    const int rx = lane & 7;
    const int aLRow = (lane & 7) + ((lane >> 3) & 1) * 8;
    const int colA = (lane >> 4) & 1;
    const int bLRow = (lane & 7) + ((lane >> 4) & 1) * 8;
    const int colB = (lane >> 3) & 1;
    const uint32_t aRowOff = (uint32_t)(warpM * 64 + aLRow) * 128;
    const uint32_t bRowOff = 16384u + (uint32_t)(warpN * 32 + bLRow) * 128;
    const uint32_t pA[2] = {(uint32_t)((colA ^ rx) << 4),
                            (uint32_t)(((2 + colA) ^ rx) << 4)};
    const uint32_t pB[2] = {(uint32_t)((colB ^ rx) << 4),
                            (uint32_t)(((2 + colB) ^ rx) << 4)};

    float acc[4][4][4];
    #pragma unroll
    for (int i = 0; i < 4; i++)
        #pragma unroll
        for (int j = 0; j < 4; j++)
            #pragma unroll
            for (int v = 0; v < 4; v++) acc[i][j][v] = 0.f;

    #define DECODE(s, cc, mB, nB) do {                                         \
        int tI_ = (s) >> kshift;                                               \
        int tile_ = blockIdx.x + tI_ * gridDim.x;                              \
        cc = (s) & kmask;                                                      \
        nB = (tile_ & 3) << 7;                                                 \
        mB = (tile_ >> 2) << 7;                                                \
    } while (0)

    #define FILL(stage, cc, mB, nB) do {                                       \
        uint32_t mb_ = sb + (stage) * 8;                                       \
        asm volatile("mbarrier.arrive.expect_tx.shared.b64 _, [%0], %1;"       \
            :: "r"(mb_), "r"(32768u) : "memory");                              \
        uint32_t d_ = bufBase + (stage) * STG_B;                               \
        asm volatile(                                                          \
            "cp.async.bulk.shared::cta.global.mbarrier::complete_tx::bytes "   \
            "[%0], [%1], %2, [%3];"                                            \
            :: "r"(d_), "l"(gA + (size_t)(cc) * CHA + (size_t)(mB) * 128),     \
               "r"(16384u), "r"(mb_) : "memory");                              \
        asm volatile(                                                          \
            "cp.async.bulk.shared::cta.global.mbarrier::complete_tx::bytes "   \
            "[%0], [%1], %2, [%3];"                                            \
            :: "r"(d_ + 16384u),                                               \
               "l"(gW + (size_t)(cc) * WCH + (size_t)(nB) * 128),              \
               "r"(16384u), "r"(mb_) : "memory");                              \
    } while (0)

    if (tid == 0) {
        asm volatile("mbarrier.init.shared.b64 [%0], 1;" :: "r"(sb) : "memory");
        asm volatile("mbarrier.init.shared.b64 [%0], 1;" :: "r"(sb + 8) : "memory");
    }
    __syncthreads();
    if (tid == 0) {
        int c0, m0, n0; DECODE(0, c0, m0, n0); FILL(0, c0, m0, n0);
        if (totalSlots > 1) { int c1, m1, n1; DECODE(1, c1, m1, n1); FILL(1, c1, m1, n1); }
    }

    int ph0 = 0, ph1 = 0;
    for (int s = 0; s < totalSlots; s++) {
        const int stage = s & 1;
        if (stage == 0) { mbar_wait(sb, ph0);     ph0 ^= 1; }
        else            { mbar_wait(sb + 8, ph1); ph1 ^= 1; }

        const uint32_t stA = bufBase + stage * STG_B;
        #pragma unroll
        for (int kkI = 0; kkI < 2; kkI++) {
            uint32_t bh[4][2], bm[4][2];
            #pragma unroll
            for (int jp = 0; jp < 2; jp++) {
                uint32_t ba = stA + bRowOff + jp * 2048 + pB[kkI];
                LDSM4(bh[2 * jp][0], bh[2 * jp][1],
                      bh[2 * jp + 1][0], bh[2 * jp + 1][1], ba);
                LDSM4(bm[2 * jp][0], bm[2 * jp][1],
                      bm[2 * jp + 1][0], bm[2 * jp + 1][1], ba ^ 64u);
            }
            #pragma unroll
            for (int i = 0; i < 4; i++) {
                uint32_t aa = stA + aRowOff + i * 2048 + pA[kkI];
                uint32_t ah0, ah1, ah2, ah3, am0, am1, am2, am3;
                LDSM4(ah0, ah1, ah2, ah3, aa);
                LDSM4(am0, am1, am2, am3, aa ^ 64u);
                #pragma unroll
                for (int j = 0; j < 4; j++) {
                    MMA_B16(acc[i][j], ah0, ah1, ah2, ah3, bh[j][0], bh[j][1]);
                    MMA_B16(acc[i][j], am0, am1, am2, am3, bh[j][0], bh[j][1]);
                    MMA_B16(acc[i][j], ah0, ah1, ah2, ah3, bm[j][0], bm[j][1]);
                }
            }
        }

        if ((s & kmask) == kmask) {
            int cE, mB, nB;
            DECODE(s, cE, mB, nB);
            #pragma unroll
            for (int j = 0; j < 4; j++) {
                int col = nB + warpN * 32 + j * 8 + 2 * t4;
                float bv0 = __ldg(&bias[col]), bv1 = __ldg(&bias[col + 1]);
                #pragma unroll
                for (int i = 0; i < 4; i++) {
                    int r0 = mB + warpM * 64 + i * 16 + g;
                    if (r0 < M) {
                        float2 v0 = make_float2(fmaxf(acc[i][j][0] + bv0, 0.f),
                                                fmaxf(acc[i][j][1] + bv1, 0.f));
                        *(float2*)(Xout + (size_t)r0 * HH + col) = v0;
                    }
                    int r1 = r0 + 8;
                    if (r1 < M) {
                        float2 v1 = make_float2(fmaxf(acc[i][j][2] + bv0, 0.f),
                                                fmaxf(acc[i][j][3] + bv1, 0.f));
                        *(float2*)(Xout + (size_t)r1 * HH + col) = v1;
                    }
                    #pragma unroll
                    for (int v = 0; v < 4; v++) acc[i][j][v] = 0.f;
                }
            }
        }
        __syncthreads();
        if (tid == 0 && s + 2 < totalSlots) {
            int cN, mN, nN;
            DECODE(s + 2, cN, mN, nN);
            FILL(stage, cN, mN, nN);
        }
    }
}

// ---------------- final small GEMM + final aggregation ----------------
__global__ void gemm_small_kernel(const float* __restrict__ X,
                                  const float* __restrict__ W1,
                                  float* __restrict__ S) {
    int row = blockIdx.x * (blockDim.x / 32) + (threadIdx.x >> 5);
    int lane = threadIdx.x & 31;
    if (row >= NN) return;
    float a0 = 0.f, a1 = 0.f, a2 = 0.f;
    const float* xr = X + (size_t)row * HH;
    for (int k = lane; k < HH; k += 32) {
        float xv = xr[k];
        a0 += xv * W1[k * 3 + 0];
        a1 += xv * W1[k * 3 + 1];
        a2 += xv * W1[k * 3 + 2];
    }
    #pragma unroll
    for (int off = 16; off; off >>= 1) {
        a0 += __shfl_down_sync(0xffffffffu, a0, off);
        a1 += __shfl_down_sync(0xffffffffu, a1, off);
        a2 += __shfl_down_sync(0xffffffffu, a2, off);
    }
    if (lane == 0) {
        S[row * 3 + 0] = a0;
        S[row * 3 + 1] = a1;
        S[row * 3 + 2] = a2;
    }
}

__global__ void agg_final_kernel(const float* __restrict__ S,
                                 const float* __restrict__ b1,
                                 float* __restrict__ out) {
    int i = blockIdx.x * blockDim.x + threadIdx.x;
    if (i >= NN) return;
    float a0 = 0.f, a1 = 0.f, a2 = 0.f;
    int beg = g_rowptr[i], end = g_rowptr[i + 1];
    for (int e = beg; e < end; e++) {
        int s = g_col[e];
        float cf = g_coef[e];
        a0 += cf * S[s * 3 + 0];
        a1 += cf * S[s * 3 + 1];
        a2 += cf * S[s * 3 + 2];
    }
    out[i * 3 + 0] = a0 + b1[0];
    out[i * 3 + 1] = a1 + b1[1];
    out[i * 3 + 2] = a2 + b1[2];
}

// ---------------- host orchestration ----------------
extern "C" void kernel_launch(void* const* d_in, const int* in_sizes, int n_in,
                              void* d_out, int out_size) {
    const float* x  = (const float*)d_in[0];
    const void*  ei = d_in[1];
    const float* W0 = (const float*)d_in[2];
    const float* b0 = (const float*)d_in[3];
    const float* Wr = (const float*)d_in[4];
    const float* br = (const float*)d_in[5];
    const float* W1 = (const float*)d_in[6];
    const float* b1 = (const float*)d_in[7];
    float* out  = (float*)d_out;
    float* outX = out + (size_t)NN * CC;

    float *gX, *gS;
    unsigned char *gA, *gW;
    int *gCnt, *gFill;
    unsigned* gIs32;
    cudaGetSymbolAddress((void**)&gX,  g_X);
    cudaGetSymbolAddress((void**)&gS,  g_S);
    cudaGetSymbolAddress((void**)&gA,  g_A);
    cudaGetSymbolAddress((void**)&gW,  g_W);
    cudaGetSymbolAddress((void**)&gCnt, g_cnt);
    cudaGetSymbolAddress((void**)&gFill, g_fill);
    cudaGetSymbolAddress((void**)&gIs32, g_is32);

    cudaFuncSetAttribute(gemm_mma_kernel,
                         cudaFuncAttributeMaxDynamicSharedMemorySize, SMEM_REQ);

    // preprocessing
    cudaMemsetAsync(gCnt, 0, NN * sizeof(int));
    cudaMemsetAsync(gFill, 0, NN * sizeof(int));
    cudaMemsetAsync(gIs32, 0, sizeof(unsigned));
    detect_kernel<<<256, 256>>>((const unsigned*)ei);
    convert_count_kernel<<<(EE + 255) / 256, 256>>>(ei);
    scan_kernel<<<1, 1024>>>();
    fill_kernel<<<(EE + 255) / 256, 256>>>();
    wsplit_kernel<<<dim3(HH, 13), 64>>>(W0, Wr);

    const int nTiles = (NPAD / 128) * 4;   // 1564
    const int gGrid = 296;                 // 2 CTAs per SM

    // layer 0: agg on F=256, then GEMM K=256
    agg_kernel<FF / 4><<<NN, FF / 4>>>(x, gA);
    gemm_mma_kernel<<<gGrid, 256, SMEM_REQ>>>(gA, gW, b0, gX, NN, nTiles, 3);

    // 12 residual-block convs
    for (int L = 1; L <= 12; L++) {
        agg_kernel<HH / 4><<<NN, HH / 4>>>(gX, gA);
        float* dst = (L == 12) ? outX : gX;
        gemm_mma_kernel<<<gGrid, 256, SMEM_REQ>>>(
            gA, gW + (size_t)L * WSLOT,
            br + (size_t)(L - 1) * HH, dst, NN, nTiles, 4);
    }

    // final conv: GEMM first (H->3), then aggregate on 3 cols + bias
    gemm_small_kernel<<<(NN + 7) / 8, 256>>>(outX, W1, gS);
    agg_final_kernel<<<(NN + 255) / 256, 256>>>(gS, b1, out);
}

// round 8
// speedup vs baseline: 1.6538x; 1.3048x over previous
#include <cuda_runtime.h>
#include <cuda_fp16.h>
#include <cstdint>

#define NN 50000
#define EE 400000
#define FF 256
#define HH 512
#define CC 3
#define NPAD 50048                        // 391 * 128
#define CHA64 ((size_t)NPAD * 128)        // A k64-chunk stride (bytes)
#define WCH ((size_t)512 * 128)           // W k32-chunk stride (bytes)
#define WSLOT ((size_t)16 * 512 * 128)    // W layer slot stride (bytes)

// ---------------- device scratch ----------------
__device__ float g_X[(size_t)NPAD * HH];                 // fp32 activations
__device__ unsigned char g_A[(size_t)8 * NPAD * 128];    // fp16 A, blocked+swizzled
__device__ unsigned char g_W[(size_t)13 * 16 * 512 * 128]; // fp16 hi|mid W blocked
__device__ float g_S[(size_t)NN * CC];
__device__ float g_dinv[NN];
__device__ float g_coef[EE + NN];
__device__ int   g_col[EE + NN];
__device__ int   g_srcA[EE];
__device__ int   g_dstA[EE];
__device__ int   g_cnt[NN];
__device__ int   g_fill[NN];
__device__ int   g_rowptr[NN + 1];
__device__ unsigned g_is32;

// ---------------- preprocessing ----------------
__global__ void detect_kernel(const unsigned* __restrict__ w) {
    unsigned local = 0;
    for (int i = blockIdx.x * blockDim.x + threadIdx.x; i < EE;
         i += gridDim.x * blockDim.x)
        local |= w[2 * i + 1];
    #pragma unroll
    for (int off = 16; off; off >>= 1)
        local |= __shfl_xor_sync(0xffffffffu, local, off);
    if ((threadIdx.x & 31) == 0 && local) atomicOr(&g_is32, 1u);
}

__global__ void convert_count_kernel(const void* __restrict__ ei) {
    int e = blockIdx.x * blockDim.x + threadIdx.x;
    if (e >= EE) return;
    int s, d;
    if (g_is32) {
        const int* p = (const int*)ei;
        s = p[e]; d = p[EE + e];
    } else {
        const long long* p = (const long long*)ei;
        s = (int)p[e]; d = (int)p[EE + e];
    }
    g_srcA[e] = s; g_dstA[e] = d;
    atomicAdd(&g_cnt[d], 1);
}

__global__ void scan_kernel() {
    __shared__ int s[1024];
    const int T = 1024;
    int tid = threadIdx.x;
    int chunk = (NN + T - 1) / T;
    int beg = tid * chunk;
    int end = min(beg + chunk, NN);
    int sum = 0;
    for (int i = beg; i < end; i++) sum += g_cnt[i] + 1;
    s[tid] = sum;
    __syncthreads();
    for (int off = 1; off < T; off <<= 1) {
        int v = (tid >= off) ? s[tid - off] : 0;
        __syncthreads();
        s[tid] += v;
        __syncthreads();
    }
    int run = (tid > 0) ? s[tid - 1] : 0;
    for (int i = beg; i < end; i++) {
        int c = g_cnt[i];
        float di = rsqrtf((float)c + 1.0f);
        g_rowptr[i] = run;
        g_dinv[i] = di;
        g_col[run + c] = i;
        g_coef[run + c] = di * di;
        run += c + 1;
    }
    if (tid == T - 1) g_rowptr[NN] = run;
}

__global__ void fill_kernel() {
    int e = blockIdx.x * blockDim.x + threadIdx.x;
    if (e >= EE) return;
    int d = g_dstA[e], s = g_srcA[e];
    int pos = g_rowptr[d] + atomicAdd(&g_fill[d], 1);
    g_col[pos]  = s;
    g_coef[pos] = g_dinv[s] * g_dinv[d];
}

// ---------------- weight split: fp16 hi|mid, blocked swizzled --------------
// block (L, kc32, n): 128 B = hi 4x16B | mid 4x16B, phys16 = c16 ^ (n&7), mid = hi^64
__global__ void wsplit_kernel(const float* __restrict__ W0,
                              const float* __restrict__ Wr) {
    int L = blockIdx.y;
    int n = blockIdx.x;
    int K = (L == 0) ? FF : HH;
    const float* W = (L == 0) ? W0 : (Wr + (size_t)(L - 1) * HH * HH);
    unsigned char* slot = g_W + (size_t)L * WSLOT;
    int t = threadIdx.x;
    if (t >= (K >> 3)) return;
    int kc = t >> 2, c16 = t & 3, k0 = t * 8;
    unsigned hw[4], mw[4];
    #pragma unroll
    for (int p = 0; p < 4; p++) {
        unsigned hlo, hhi, mlo, mhi;
        {
            float x = W[(size_t)(k0 + 2 * p) * HH + n];
            __half h = __float2half_rn(x);
            float r = x - __half2float(h);
            hlo = (unsigned)__half_as_ushort(h);
            mlo = (unsigned)__half_as_ushort(__float2half_rn(r));
        }
        {
            float x = W[(size_t)(k0 + 2 * p + 1) * HH + n];
            __half h = __float2half_rn(x);
            float r = x - __half2float(h);
            hhi = (unsigned)__half_as_ushort(h);
            mhi = (unsigned)__half_as_ushort(__float2half_rn(r));
        }
        hw[p] = hlo | (hhi << 16);
        mw[p] = mlo | (mhi << 16);
    }
    unsigned char* base = slot + (size_t)kc * WCH + (size_t)n * 128;
    uint32_t physHi = ((uint32_t)(c16 ^ (n & 7))) << 4;
    *(uint4*)(base + physHi) = make_uint4(hw[0], hw[1], hw[2], hw[3]);
    *(uint4*)(base + (physHi ^ 64)) = make_uint4(mw[0], mw[1], mw[2], mw[3]);
}

// ---------------- aggregation -> fp16 blocked swizzled ----------------
// A block (kc64, node): 128 B = 8 x 16B units (8 k each), phys = u ^ (node&7)
template <int W4>
__global__ void agg_kernel(const float* __restrict__ X,
                           unsigned char* __restrict__ gA) {
    int node = blockIdx.x;
    int t = threadIdx.x;
    const float4* Xv = (const float4*)X;
    float4 acc = make_float4(0.f, 0.f, 0.f, 0.f);
    int beg = g_rowptr[node], end = g_rowptr[node + 1];
    for (int e = beg; e < end; e++) {
        int s = g_col[e];
        float cf = g_coef[e];
        float4 v = Xv[(size_t)s * W4 + t];
        acc.x += cf * v.x; acc.y += cf * v.y;
        acc.z += cf * v.z; acc.w += cf * v.w;
    }
    unsigned h0 = (unsigned)__half_as_ushort(__float2half_rn(acc.x));
    unsigned h1 = (unsigned)__half_as_ushort(__float2half_rn(acc.y));
    unsigned h2 = (unsigned)__half_as_ushort(__float2half_rn(acc.z));
    unsigned h3 = (unsigned)__half_as_ushort(__float2half_rn(acc.w));
    uint2 ph;
    ph.x = h0 | (h1 << 16); ph.y = h2 | (h3 << 16);
    int kc = t >> 4;                  // k64 chunk
    int u  = (t >> 1) & 7;            // 16B unit
    int off = (t & 1) * 8;            // half of unit
    unsigned char* base = gA + (size_t)kc * CHA64 + (size_t)node * 128;
    uint32_t phys = ((uint32_t)(u ^ (node & 7))) << 4;
    *(uint2*)(base + phys + off) = ph;
}

// ---------------- persistent HMMA fp16x2 GEMM with TMA bulk staging --------
// Block tile 128x128, 8 warps, BK=64. Stage = A 16KB + B 32KB; 2 stages.
#define STG_B   49152
#define SMEM_REQ (1024 + 128 + 2 * STG_B)

#define MMA_F16(cc, A0, A1, A2, A3, B0, B1)                                   \
    asm volatile(                                                             \
        "mma.sync.aligned.m16n8k16.row.col.f32.f16.f16.f32 "                  \
        "{%0,%1,%2,%3}, {%4,%5,%6,%7}, {%8,%9}, {%0,%1,%2,%3};"               \
        : "+f"(cc[0]), "+f"(cc[1]), "+f"(cc[2]), "+f"(cc[3])                  \
        : "r"(A0), "r"(A1), "r"(A2), "r"(A3), "r"(B0), "r"(B1))

#define LDSM4(r0, r1, r2, r3, addr)                                           \
    asm volatile("ldmatrix.sync.aligned.m8n8.x4.shared.b16 {%0,%1,%2,%3}, [%4];" \
        : "=r"(r0), "=r"(r1), "=r"(r2), "=r"(r3) : "r"(addr))

__device__ __forceinline__ void mbar_wait(uint32_t mb, uint32_t parity) {
    uint32_t done;
    asm volatile("{\n\t.reg .pred p;\n\t"
                 "mbarrier.try_wait.parity.shared.b64 p, [%1], %2;\n\t"
                 "selp.b32 %0, 1, 0, p;\n\t}"
                 : "=r"(done) : "r"(mb), "r"(parity) : "memory");
    if (!done) {
        asm volatile("{\n\t.reg .pred P1;\n\t"
                     "WL_%=:\n\t"
                     "mbarrier.try_wait.parity.shared.b64 P1, [%0], %1;\n\t"
                     "@P1 bra.uni WD_%=;\n\t"
                     "bra.uni WL_%=;\n\t"
                     "WD_%=:\n\t}" :: "r"(mb), "r"(parity) : "memory");
    }
}

__global__ void __launch_bounds__(256, 2) gemm_mma_kernel(
    const unsigned char* __restrict__ gA,
    const unsigned char* __restrict__ gW,
    const float* __restrict__ bias, float* __restrict__ Xout,
    int M, int nTiles, int kshift) {
    extern __shared__ char smb[];
    uint32_t sraw;
    asm("{ .reg .u64 t; cvta.to.shared.u64 t, %1; cvt.u32.u64 %0, t; }"
        : "=r"(sraw) : "l"(smb));
    const uint32_t sb = (sraw + 1023) & ~1023u;
    const uint32_t bufBase = sb + 128;

    const int tid = threadIdx.x;
    const int lane = tid & 31, wid = tid >> 5;
    const int g = lane >> 2, t4 = lane & 3;
    const int warpM = wid & 1, warpN = wid >> 1;
    const int kmask = (1 << kshift) - 1;
    const int myTiles = (nTiles - blockIdx.x + gridDim.x - 1) / gridDim.x;
    const int totalSlots = myTiles << kshift;

    // fragment geometry
    const int rx = lane & 7;
    const int aLRow = (lane & 7) + ((lane >> 3) & 1) * 8;
    const int colA = (lane >> 4) & 1;
    const int bLRow = (lane & 7) + ((lane >> 4) & 1) * 8;
    const int colB = (lane >> 3) & 1;
    const uint32_t aRowOff = (uint32_t)(warpM * 64 + aLRow) * 128;
    const uint32_t bRowOff = 16384u + (uint32_t)(warpN * 32 + bLRow) * 128;
    uint32_t pA[4], pBc[2];
    #pragma unroll
    for (int j = 0; j < 4; j++) pA[j] = (uint32_t)(((2 * j + colA) ^ rx) << 4);
    #pragma unroll
    for (int jb = 0; jb < 2; jb++) pBc[jb] = (uint32_t)(((2 * jb + colB) ^ rx) << 4);

    float acc[4][4][4];
    #pragma unroll
    for (int i = 0; i < 4; i++)
        #pragma unroll
        for (int j = 0; j < 4; j++)
            #pragma unroll
            for (int v = 0; v < 4; v++) acc[i][j][v] = 0.f;

    #define DECODE(s, cc, mB, nB) do {                                         \
        int tI_ = (s) >> kshift;                                               \
        int tile_ = blockIdx.x + tI_ * gridDim.x;                              \
        cc = (s) & kmask;                                                      \
        nB = (tile_ & 3) << 7;                                                 \
        mB = (tile_ >> 2) << 7;                                                \
    } while (0)

    #define FILL(stage, cc, mB, nB) do {                                       \
        uint32_t mb_ = sb + (stage) * 8;                                       \
        asm volatile("mbarrier.arrive.expect_tx.shared.b64 _, [%0], %1;"       \
            :: "r"(mb_), "r"(49152u) : "memory");                              \
        uint32_t d_ = bufBase + (stage) * STG_B;                               \
        asm volatile(                                                          \
            "cp.async.bulk.shared::cta.global.mbarrier::complete_tx::bytes "   \
            "[%0], [%1], %2, [%3];"                                            \
            :: "r"(d_), "l"(gA + (size_t)(cc) * CHA64 + (size_t)(mB) * 128),   \
               "r"(16384u), "r"(mb_) : "memory");                              \
        asm volatile(                                                          \
            "cp.async.bulk.shared::cta.global.mbarrier::complete_tx::bytes "   \
            "[%0], [%1], %2, [%3];"                                            \
            :: "r"(d_ + 16384u),                                               \
               "l"(gW + (size_t)(2 * (cc)) * WCH + (size_t)(nB) * 128),        \
               "r"(16384u), "r"(mb_) : "memory");                              \
        asm volatile(                                                          \
            "cp.async.bulk.shared::cta.global.mbarrier::complete_tx::bytes "   \
            "[%0], [%1], %2, [%3];"                                            \
            :: "r"(d_ + 32768u),                                               \
               "l"(gW + (size_t)(2 * (cc) + 1) * WCH + (size_t)(nB) * 128),    \
               "r"(16384u), "r"(mb_) : "memory");                              \
    } while (0)

    if (tid == 0) {
        asm volatile("mbarrier.init.shared.b64 [%0], 1;" :: "r"(sb) : "memory");
        asm volatile("mbarrier.init.shared.b64 [%0], 1;" :: "r"(sb + 8) : "memory");
    }
    __syncthreads();
    if (tid == 0) {
        int c0, m0, n0; DECODE(0, c0, m0, n0); FILL(0, c0, m0, n0);
        if (totalSlots > 1) { int c1, m1, n1; DECODE(1, c1, m1, n1); FILL(1, c1, m1, n1); }
    }

    int ph0 = 0, ph1 = 0;
    for (int s = 0; s < totalSlots; s++) {
        const int stage = s & 1;
        if (stage == 0) { mbar_wait(sb, ph0);     ph0 ^= 1; }
        else            { mbar_wait(sb + 8, ph1); ph1 ^= 1; }

        const uint32_t stA = bufBase + stage * STG_B;
        #pragma unroll
        for (int j = 0; j < 4; j++) {                  // kk16 within k64
            const uint32_t sub = (uint32_t)(j >> 1) * 16384u;
            uint32_t bh[4][2], bm[4][2];
            #pragma unroll
            for (int jp = 0; jp < 2; jp++) {
                uint32_t ba = stA + bRowOff + sub + jp * 2048u + pBc[j & 1];
                LDSM4(bh[2 * jp][0], bh[2 * jp][1],
                      bh[2 * jp + 1][0], bh[2 * jp + 1][1], ba);
                LDSM4(bm[2 * jp][0], bm[2 * jp][1],
                      bm[2 * jp + 1][0], bm[2 * jp + 1][1], ba ^ 64u);
            }
            #pragma unroll
            for (int i = 0; i < 4; i++) {
                uint32_t aa = stA + aRowOff + i * 2048u + pA[j];
                uint32_t a0, a1, a2, a3;
                LDSM4(a0, a1, a2, a3, aa);
                #pragma unroll
                for (int jn = 0; jn < 4; jn++) {
                    MMA_F16(acc[i][jn], a0, a1, a2, a3, bh[jn][0], bh[jn][1]);
                    MMA_F16(acc[i][jn], a0, a1, a2, a3, bm[jn][0], bm[jn][1]);
                }
            }
        }

        if ((s & kmask) == kmask) {
            int cE, mB, nB;
            DECODE(s, cE, mB, nB);
            #pragma unroll
            for (int j = 0; j < 4; j++) {
                int col = nB + warpN * 32 + j * 8 + 2 * t4;
                float bv0 = __ldg(&bias[col]), bv1 = __ldg(&bias[col + 1]);
                #pragma unroll
                for (int i = 0; i < 4; i++) {
                    int r0 = mB + warpM * 64 + i * 16 + g;
                    if (r0 < M) {
                        float2 v0 = make_float2(fmaxf(acc[i][j][0] + bv0, 0.f),
                                                fmaxf(acc[i][j][1] + bv1, 0.f));
                        *(float2*)(Xout + (size_t)r0 * HH + col) = v0;
                    }
                    int r1 = r0 + 8;
                    if (r1 < M) {
                        float2 v1 = make_float2(fmaxf(acc[i][j][2] + bv0, 0.f),
                                                fmaxf(acc[i][j][3] + bv1, 0.f));
                        *(float2*)(Xout + (size_t)r1 * HH + col) = v1;
                    }
                    #pragma unroll
                    for (int v = 0; v < 4; v++) acc[i][j][v] = 0.f;
                }
            }
        }
        __syncthreads();
        if (tid == 0 && s + 2 < totalSlots) {
            int cN, mN, nN;
            DECODE(s + 2, cN, mN, nN);
            FILL(stage, cN, mN, nN);
        }
    }
}

// ---------------- final small GEMM + final aggregation ----------------
__global__ void gemm_small_kernel(const float* __restrict__ X,
                                  const float* __restrict__ W1,
                                  float* __restrict__ S) {
    int row = blockIdx.x * (blockDim.x / 32) + (threadIdx.x >> 5);
    int lane = threadIdx.x & 31;
    if (row >= NN) return;
    float a0 = 0.f, a1 = 0.f, a2 = 0.f;
    const float* xr = X + (size_t)row * HH;
    for (int k = lane; k < HH; k += 32) {
        float xv = xr[k];
        a0 += xv * W1[k * 3 + 0];
        a1 += xv * W1[k * 3 + 1];
        a2 += xv * W1[k * 3 + 2];
    }
    #pragma unroll
    for (int off = 16; off; off >>= 1) {
        a0 += __shfl_down_sync(0xffffffffu, a0, off);
        a1 += __shfl_down_sync(0xffffffffu, a1, off);
        a2 += __shfl_down_sync(0xffffffffu, a2, off);
    }
    if (lane == 0) {
        S[row * 3 + 0] = a0;
        S[row * 3 + 1] = a1;
        S[row * 3 + 2] = a2;
    }
}

__global__ void agg_final_kernel(const float* __restrict__ S,
                                 const float* __restrict__ b1,
                                 float* __restrict__ out) {
    int i = blockIdx.x * blockDim.x + threadIdx.x;
    if (i >= NN) return;
    float a0 = 0.f, a1 = 0.f, a2 = 0.f;
    int beg = g_rowptr[i], end = g_rowptr[i + 1];
    for (int e = beg; e < end; e++) {
        int s = g_col[e];
        float cf = g_coef[e];
        a0 += cf * S[s * 3 + 0];
        a1 += cf * S[s * 3 + 1];
        a2 += cf * S[s * 3 + 2];
    }
    out[i * 3 + 0] = a0 + b1[0];
    out[i * 3 + 1] = a1 + b1[1];
    out[i * 3 + 2] = a2 + b1[2];
}

// ---------------- host orchestration ----------------
extern "C" void kernel_launch(void* const* d_in, const int* in_sizes, int n_in,
                              void* d_out, int out_size) {
    const float* x  = (const float*)d_in[0];
    const void*  ei = d_in[1];
    const float* W0 = (const float*)d_in[2];
    const float* b0 = (const float*)d_in[3];
    const float* Wr = (const float*)d_in[4];
    const float* br = (const float*)d_in[5];
    const float* W1 = (const float*)d_in[6];
    const float* b1 = (const float*)d_in[7];
    float* out  = (float*)d_out;
    float* outX = out + (size_t)NN * CC;

    float *gX, *gS;
    unsigned char *gA, *gW;
    int *gCnt, *gFill;
    unsigned* gIs32;
    cudaGetSymbolAddress((void**)&gX,  g_X);
    cudaGetSymbolAddress((void**)&gS,  g_S);
    cudaGetSymbolAddress((void**)&gA,  g_A);
    cudaGetSymbolAddress((void**)&gW,  g_W);
    cudaGetSymbolAddress((void**)&gCnt, g_cnt);
    cudaGetSymbolAddress((void**)&gFill, g_fill);
    cudaGetSymbolAddress((void**)&gIs32, g_is32);

    cudaFuncSetAttribute(gemm_mma_kernel,
                         cudaFuncAttributeMaxDynamicSharedMemorySize, SMEM_REQ);

    // preprocessing
    cudaMemsetAsync(gCnt, 0, NN * sizeof(int));
    cudaMemsetAsync(gFill, 0, NN * sizeof(int));
    cudaMemsetAsync(gIs32, 0, sizeof(unsigned));
    detect_kernel<<<256, 256>>>((const unsigned*)ei);
    convert_count_kernel<<<(EE + 255) / 256, 256>>>(ei);
    scan_kernel<<<1, 1024>>>();
    fill_kernel<<<(EE + 255) / 256, 256>>>();
    wsplit_kernel<<<dim3(HH, 13), 64>>>(W0, Wr);

    const int nTiles = (NPAD / 128) * 4;   // 1564
    const int gGrid = 296;                 // 2 CTAs per SM

    // layer 0: agg on F=256, then GEMM K=256 (4 k64 slots/tile)
    agg_kernel<FF / 4><<<NN, FF / 4>>>(x, gA);
    gemm_mma_kernel<<<gGrid, 256, SMEM_REQ>>>(gA, gW, b0, gX, NN, nTiles, 2);

    // 12 residual-block convs (8 k64 slots/tile)
    for (int L = 1; L <= 12; L++) {
        agg_kernel<HH / 4><<<NN, HH / 4>>>(gX, gA);
        float* dst = (L == 12) ? outX : gX;
        gemm_mma_kernel<<<gGrid, 256, SMEM_REQ>>>(
            gA, gW + (size_t)L * WSLOT,
            br + (size_t)(L - 1) * HH, dst, NN, nTiles, 3);
    }

    // final conv: GEMM first (H->3), then aggregate on 3 cols + bias
    gemm_small_kernel<<<(NN + 7) / 8, 256>>>(outX, W1, gS);
    agg_final_kernel<<<(NN + 255) / 256, 256>>>(gS, b1, out);
}

// round 9
// speedup vs baseline: 2.0342x; 1.2300x over previous
#include <cuda_runtime.h>
#include <cuda_fp16.h>
#include <cstdint>

#define NN 50000
#define EE 400000
#define FF 256
#define HH 512
#define CC 3
#define NPAD 50048                        // 391 * 128
#define CHA64 ((size_t)NPAD * 128)        // A k64-chunk stride (bytes)
#define WCH ((size_t)512 * 128)           // W k32-chunk stride (bytes)
#define WSLOT ((size_t)16 * 512 * 128)    // W layer slot stride (bytes)

// ---------------- device scratch ----------------
__device__ __half g_X16[(size_t)NPAD * HH];              // fp16 activations
__device__ unsigned char g_A[(size_t)8 * NPAD * 128];    // fp16 A, blocked+swizzled
__device__ unsigned char g_W[(size_t)13 * 16 * 512 * 128]; // fp16 hi|mid W blocked
__device__ float g_S[(size_t)NN * CC];
__device__ float g_dinv[NN];
__device__ float g_coef[EE + NN];
__device__ int   g_col[EE + NN];
__device__ int   g_srcA[EE];
__device__ int   g_dstA[EE];
__device__ int   g_cnt[NN];
__device__ int   g_fill[NN];
__device__ int   g_rowptr[NN + 1];
__device__ unsigned g_is32;

// ---------------- preprocessing ----------------
__global__ void detect_kernel(const unsigned* __restrict__ w) {
    unsigned local = 0;
    for (int i = blockIdx.x * blockDim.x + threadIdx.x; i < EE;
         i += gridDim.x * blockDim.x)
        local |= w[2 * i + 1];
    #pragma unroll
    for (int off = 16; off; off >>= 1)
        local |= __shfl_xor_sync(0xffffffffu, local, off);
    if ((threadIdx.x & 31) == 0 && local) atomicOr(&g_is32, 1u);
}

__global__ void convert_count_kernel(const void* __restrict__ ei) {
    int e = blockIdx.x * blockDim.x + threadIdx.x;
    if (e >= EE) return;
    int s, d;
    if (g_is32) {
        const int* p = (const int*)ei;
        s = p[e]; d = p[EE + e];
    } else {
        const long long* p = (const long long*)ei;
        s = (int)p[e]; d = (int)p[EE + e];
    }
    g_srcA[e] = s; g_dstA[e] = d;
    atomicAdd(&g_cnt[d], 1);
}

__global__ void scan_kernel() {
    __shared__ int s[1024];
    const int T = 1024;
    int tid = threadIdx.x;
    int chunk = (NN + T - 1) / T;
    int beg = tid * chunk;
    int end = min(beg + chunk, NN);
    int sum = 0;
    for (int i = beg; i < end; i++) sum += g_cnt[i] + 1;
    s[tid] = sum;
    __syncthreads();
    for (int off = 1; off < T; off <<= 1) {
        int v = (tid >= off) ? s[tid - off] : 0;
        __syncthreads();
        s[tid] += v;
        __syncthreads();
    }
    int run = (tid > 0) ? s[tid - 1] : 0;
    for (int i = beg; i < end; i++) {
        int c = g_cnt[i];
        float di = rsqrtf((float)c + 1.0f);
        g_rowptr[i] = run;
        g_dinv[i] = di;
        g_col[run + c] = i;
        g_coef[run + c] = di * di;
        run += c + 1;
    }
    if (tid == T - 1) g_rowptr[NN] = run;
}

__global__ void fill_kernel() {
    int e = blockIdx.x * blockDim.x + threadIdx.x;
    if (e >= EE) return;
    int d = g_dstA[e], s = g_srcA[e];
    int pos = g_rowptr[d] + atomicAdd(&g_fill[d], 1);
    g_col[pos]  = s;
    g_coef[pos] = g_dinv[s] * g_dinv[d];
}

// ---------------- weight split: fp16 hi|mid, blocked swizzled --------------
__global__ void wsplit_kernel(const float* __restrict__ W0,
                              const float* __restrict__ Wr) {
    int L = blockIdx.y;
    int n = blockIdx.x;
    int K = (L == 0) ? FF : HH;
    const float* W = (L == 0) ? W0 : (Wr + (size_t)(L - 1) * HH * HH);
    unsigned char* slot = g_W + (size_t)L * WSLOT;
    int t = threadIdx.x;
    if (t >= (K >> 3)) return;
    int kc = t >> 2, c16 = t & 3, k0 = t * 8;
    unsigned hw[4], mw[4];
    #pragma unroll
    for (int p = 0; p < 4; p++) {
        unsigned hlo, hhi, mlo, mhi;
        {
            float x = W[(size_t)(k0 + 2 * p) * HH + n];
            __half h = __float2half_rn(x);
            float r = x - __half2float(h);
            hlo = (unsigned)__half_as_ushort(h);
            mlo = (unsigned)__half_as_ushort(__float2half_rn(r));
        }
        {
            float x = W[(size_t)(k0 + 2 * p + 1) * HH + n];
            __half h = __float2half_rn(x);
            float r = x - __half2float(h);
            hhi = (unsigned)__half_as_ushort(h);
            mhi = (unsigned)__half_as_ushort(__float2half_rn(r));
        }
        hw[p] = hlo | (hhi << 16);
        mw[p] = mlo | (mhi << 16);
    }
    unsigned char* base = slot + (size_t)kc * WCH + (size_t)n * 128;
    uint32_t physHi = ((uint32_t)(c16 ^ (n & 7))) << 4;
    *(uint4*)(base + physHi) = make_uint4(hw[0], hw[1], hw[2], hw[3]);
    *(uint4*)(base + (physHi ^ 64)) = make_uint4(mw[0], mw[1], mw[2], mw[3]);
}

// ---------------- layer-0 aggregation (fp32 input x) -> fp16 blocked A -----
// 64 threads, thread t handles k = 4t..4t+3 (FF=256)
__global__ void agg_kernel(const float* __restrict__ X,
                           unsigned char* __restrict__ gA) {
    int node = blockIdx.x;
    int t = threadIdx.x;
    const float4* Xv = (const float4*)X;
    float4 acc = make_float4(0.f, 0.f, 0.f, 0.f);
    int beg = g_rowptr[node], end = g_rowptr[node + 1];
    for (int e = beg; e < end; e++) {
        int s = g_col[e];
        float cf = g_coef[e];
        float4 v = Xv[(size_t)s * (FF / 4) + t];
        acc.x += cf * v.x; acc.y += cf * v.y;
        acc.z += cf * v.z; acc.w += cf * v.w;
    }
    unsigned h0 = (unsigned)__half_as_ushort(__float2half_rn(acc.x));
    unsigned h1 = (unsigned)__half_as_ushort(__float2half_rn(acc.y));
    unsigned h2 = (unsigned)__half_as_ushort(__float2half_rn(acc.z));
    unsigned h3 = (unsigned)__half_as_ushort(__float2half_rn(acc.w));
    uint2 ph;
    ph.x = h0 | (h1 << 16); ph.y = h2 | (h3 << 16);
    int kc = t >> 4;
    int u  = (t >> 1) & 7;
    int off = (t & 1) * 8;
    unsigned char* base = gA + (size_t)kc * CHA64 + (size_t)node * 128;
    uint32_t phys = ((uint32_t)(u ^ (node & 7))) << 4;
    *(uint2*)(base + phys + off) = ph;
}

// ---------------- mid-layer aggregation (fp16 X) -> fp16 blocked A ---------
// 64 threads, thread t handles k = 8t..8t+7 (HH=512): one uint4 per row.
__global__ void agg16_kernel(const __half* __restrict__ X,
                             unsigned char* __restrict__ gA) {
    int node = blockIdx.x;
    int t = threadIdx.x;
    const uint4* Xv = (const uint4*)X;    // row stride = 512*2/16 = 64
    float acc[8];
    #pragma unroll
    for (int i = 0; i < 8; i++) acc[i] = 0.f;
    int beg = g_rowptr[node], end = g_rowptr[node + 1];
    for (int e = beg; e < end; e++) {
        int s = g_col[e];
        float cf = g_coef[e];
        uint4 v = Xv[(size_t)s * 64 + t];
        float2 f0 = __half22float2(*(__half2*)&v.x);
        float2 f1 = __half22float2(*(__half2*)&v.y);
        float2 f2 = __half22float2(*(__half2*)&v.z);
        float2 f3 = __half22float2(*(__half2*)&v.w);
        acc[0] += cf * f0.x; acc[1] += cf * f0.y;
        acc[2] += cf * f1.x; acc[3] += cf * f1.y;
        acc[4] += cf * f2.x; acc[5] += cf * f2.y;
        acc[6] += cf * f3.x; acc[7] += cf * f3.y;
    }
    uint4 ph;
    {
        __half2 p0 = __floats2half2_rn(acc[0], acc[1]);
        __half2 p1 = __floats2half2_rn(acc[2], acc[3]);
        __half2 p2 = __floats2half2_rn(acc[4], acc[5]);
        __half2 p3 = __floats2half2_rn(acc[6], acc[7]);
        ph.x = *(unsigned*)&p0; ph.y = *(unsigned*)&p1;
        ph.z = *(unsigned*)&p2; ph.w = *(unsigned*)&p3;
    }
    int kc = t >> 3;                 // k64 chunk
    int u  = t & 7;                  // 16B unit
    unsigned char* base = gA + (size_t)kc * CHA64 + (size_t)node * 128;
    uint32_t phys = ((uint32_t)(u ^ (node & 7))) << 4;
    *(uint4*)(base + phys) = ph;
}

// ---------------- persistent HMMA fp16x2 GEMM with TMA bulk staging --------
#define STG_B   49152
#define SMEM_REQ (1024 + 128 + 2 * STG_B)

#define MMA_F16(cc, A0, A1, A2, A3, B0, B1)                                   \
    asm volatile(                                                             \
        "mma.sync.aligned.m16n8k16.row.col.f32.f16.f16.f32 "                  \
        "{%0,%1,%2,%3}, {%4,%5,%6,%7}, {%8,%9}, {%0,%1,%2,%3};"               \
        : "+f"(cc[0]), "+f"(cc[1]), "+f"(cc[2]), "+f"(cc[3])                  \
        : "r"(A0), "r"(A1), "r"(A2), "r"(A3), "r"(B0), "r"(B1))

#define LDSM4(r0, r1, r2, r3, addr)                                           \
    asm volatile("ldmatrix.sync.aligned.m8n8.x4.shared.b16 {%0,%1,%2,%3}, [%4];" \
        : "=r"(r0), "=r"(r1), "=r"(r2), "=r"(r3) : "r"(addr))

__device__ __forceinline__ void mbar_wait(uint32_t mb, uint32_t parity) {
    uint32_t done;
    asm volatile("{\n\t.reg .pred p;\n\t"
                 "mbarrier.try_wait.parity.shared.b64 p, [%1], %2;\n\t"
                 "selp.b32 %0, 1, 0, p;\n\t}"
                 : "=r"(done) : "r"(mb), "r"(parity) : "memory");
    if (!done) {
        asm volatile("{\n\t.reg .pred P1;\n\t"
                     "WL_%=:\n\t"
                     "mbarrier.try_wait.parity.shared.b64 P1, [%0], %1;\n\t"
                     "@P1 bra.uni WD_%=;\n\t"
                     "bra.uni WL_%=;\n\t"
                     "WD_%=:\n\t}" :: "r"(mb), "r"(parity) : "memory");
    }
}

template <int OUT16>
__global__ void __launch_bounds__(256, 2) gemm_mma_kernel(
    const unsigned char* __restrict__ gA,
    const unsigned char* __restrict__ gW,
    const float* __restrict__ bias, void* __restrict__ XoutV,
    int M, int nTiles, int kshift) {
    extern __shared__ char smb[];
    uint32_t sraw;
    asm("{ .reg .u64 t; cvta.to.shared.u64 t, %1; cvt.u32.u64 %0, t; }"
        : "=r"(sraw) : "l"(smb));
    const uint32_t sb = (sraw + 1023) & ~1023u;
    const uint32_t bufBase = sb + 128;

    const int tid = threadIdx.x;
    const int lane = tid & 31, wid = tid >> 5;
    const int g = lane >> 2, t4 = lane & 3;
    const int warpM = wid & 1, warpN = wid >> 1;
    const int kmask = (1 << kshift) - 1;
    const int myTiles = (nTiles - blockIdx.x + gridDim.x - 1) / gridDim.x;
    const int totalSlots = myTiles << kshift;

    const int rx = lane & 7;
    const int aLRow = (lane & 7) + ((lane >> 3) & 1) * 8;
    const int colA = (lane >> 4) & 1;
    const int bLRow = (lane & 7) + ((lane >> 4) & 1) * 8;
    const int colB = (lane >> 3) & 1;
    const uint32_t aRowOff = (uint32_t)(warpM * 64 + aLRow) * 128;
    const uint32_t bRowOff = 16384u + (uint32_t)(warpN * 32 + bLRow) * 128;
    uint32_t pA[4], pBc[2];
    #pragma unroll
    for (int j = 0; j < 4; j++) pA[j] = (uint32_t)(((2 * j + colA) ^ rx) << 4);
    #pragma unroll
    for (int jb = 0; jb < 2; jb++) pBc[jb] = (uint32_t)(((2 * jb + colB) ^ rx) << 4);

    float acc[4][4][4];
    #pragma unroll
    for (int i = 0; i < 4; i++)
        #pragma unroll
        for (int j = 0; j < 4; j++)
            #pragma unroll
            for (int v = 0; v < 4; v++) acc[i][j][v] = 0.f;

    #define DECODE(s, cc, mB, nB) do {                                         \
        int tI_ = (s) >> kshift;                                               \
        int tile_ = blockIdx.x + tI_ * gridDim.x;                              \
        cc = (s) & kmask;                                                      \
        nB = (tile_ & 3) << 7;                                                 \
        mB = (tile_ >> 2) << 7;                                                \
    } while (0)

    #define FILL(stage, cc, mB, nB) do {                                       \
        uint32_t mb_ = sb + (stage) * 8;                                       \
        asm volatile("mbarrier.arrive.expect_tx.shared.b64 _, [%0], %1;"       \
            :: "r"(mb_), "r"(49152u) : "memory");                              \
        uint32_t d_ = bufBase + (stage) * STG_B;                               \
        asm volatile(                                                          \
            "cp.async.bulk.shared::cta.global.mbarrier::complete_tx::bytes "   \
            "[%0], [%1], %2, [%3];"                                            \
            :: "r"(d_), "l"(gA + (size_t)(cc) * CHA64 + (size_t)(mB) * 128),   \
               "r"(16384u), "r"(mb_) : "memory");                              \
        asm volatile(                                                          \
            "cp.async.bulk.shared::cta.global.mbarrier::complete_tx::bytes "   \
            "[%0], [%1], %2, [%3];"                                            \
            :: "r"(d_ + 16384u),                                               \
               "l"(gW + (size_t)(2 * (cc)) * WCH + (size_t)(nB) * 128),        \
               "r"(16384u), "r"(mb_) : "memory");                              \
        asm volatile(                                                          \
            "cp.async.bulk.shared::cta.global.mbarrier::complete_tx::bytes "   \
            "[%0], [%1], %2, [%3];"                                            \
            :: "r"(d_ + 32768u),                                               \
               "l"(gW + (size_t)(2 * (cc) + 1) * WCH + (size_t)(nB) * 128),    \
               "r"(16384u), "r"(mb_) : "memory");                              \
    } while (0)

    if (tid == 0) {
        asm volatile("mbarrier.init.shared.b64 [%0], 1;" :: "r"(sb) : "memory");
        asm volatile("mbarrier.init.shared.b64 [%0], 1;" :: "r"(sb + 8) : "memory");
    }
    __syncthreads();
    if (tid == 0) {
        int c0, m0, n0; DECODE(0, c0, m0, n0); FILL(0, c0, m0, n0);
        if (totalSlots > 1) { int c1, m1, n1; DECODE(1, c1, m1, n1); FILL(1, c1, m1, n1); }
    }

    int ph0 = 0, ph1 = 0;
    for (int s = 0; s < totalSlots; s++) {
        const int stage = s & 1;
        if (stage == 0) { mbar_wait(sb, ph0);     ph0 ^= 1; }
        else            { mbar_wait(sb + 8, ph1); ph1 ^= 1; }

        const uint32_t stA = bufBase + stage * STG_B;
        #pragma unroll
        for (int j = 0; j < 4; j++) {
            const uint32_t sub = (uint32_t)(j >> 1) * 16384u;
            uint32_t bh[4][2], bm[4][2];
            #pragma unroll
            for (int jp = 0; jp < 2; jp++) {
                uint32_t ba = stA + bRowOff + sub + jp * 2048u + pBc[j & 1];
                LDSM4(bh[2 * jp][0], bh[2 * jp][1],
                      bh[2 * jp + 1][0], bh[2 * jp + 1][1], ba);
                LDSM4(bm[2 * jp][0], bm[2 * jp][1],
                      bm[2 * jp + 1][0], bm[2 * jp + 1][1], ba ^ 64u);
            }
            #pragma unroll
            for (int i = 0; i < 4; i++) {
                uint32_t aa = stA + aRowOff + i * 2048u + pA[j];
                uint32_t a0, a1, a2, a3;
                LDSM4(a0, a1, a2, a3, aa);
                #pragma unroll
                for (int jn = 0; jn < 4; jn++) {
                    MMA_F16(acc[i][jn], a0, a1, a2, a3, bh[jn][0], bh[jn][1]);
                    MMA_F16(acc[i][jn], a0, a1, a2, a3, bm[jn][0], bm[jn][1]);
                }
            }
        }

        if ((s & kmask) == kmask) {
            int cE, mB, nB;
            DECODE(s, cE, mB, nB);
            #pragma unroll
            for (int j = 0; j < 4; j++) {
                int col = nB + warpN * 32 + j * 8 + 2 * t4;
                float bv0 = __ldg(&bias[col]), bv1 = __ldg(&bias[col + 1]);
                #pragma unroll
                for (int i = 0; i < 4; i++) {
                    int r0 = mB + warpM * 64 + i * 16 + g;
                    int r1 = r0 + 8;
                    if (OUT16) {
                        __half* Xout = (__half*)XoutV;
                        if (r0 < M) {
                            __half2 v0 = __floats2half2_rn(
                                fmaxf(acc[i][j][0] + bv0, 0.f),
                                fmaxf(acc[i][j][1] + bv1, 0.f));
                            *(__half2*)(Xout + (size_t)r0 * HH + col) = v0;
                        }
                        if (r1 < M) {
                            __half2 v1 = __floats2half2_rn(
                                fmaxf(acc[i][j][2] + bv0, 0.f),
                                fmaxf(acc[i][j][3] + bv1, 0.f));
                            *(__half2*)(Xout + (size_t)r1 * HH + col) = v1;
                        }
                    } else {
                        float* Xout = (float*)XoutV;
                        if (r0 < M) {
                            float2 v0 = make_float2(fmaxf(acc[i][j][0] + bv0, 0.f),
                                                    fmaxf(acc[i][j][1] + bv1, 0.f));
                            *(float2*)(Xout + (size_t)r0 * HH + col) = v0;
                        }
                        if (r1 < M) {
                            float2 v1 = make_float2(fmaxf(acc[i][j][2] + bv0, 0.f),
                                                    fmaxf(acc[i][j][3] + bv1, 0.f));
                            *(float2*)(Xout + (size_t)r1 * HH + col) = v1;
                        }
                    }
                    #pragma unroll
                    for (int v = 0; v < 4; v++) acc[i][j][v] = 0.f;
                }
            }
        }
        __syncthreads();
        if (tid == 0 && s + 2 < totalSlots) {
            int cN, mN, nN;
            DECODE(s + 2, cN, mN, nN);
            FILL(stage, cN, mN, nN);
        }
    }
}

// ---------------- final small GEMM + final aggregation ----------------
__global__ void gemm_small_kernel(const float* __restrict__ X,
                                  const float* __restrict__ W1,
                                  float* __restrict__ S) {
    int row = blockIdx.x * (blockDim.x / 32) + (threadIdx.x >> 5);
    int lane = threadIdx.x & 31;
    if (row >= NN) return;
    float a0 = 0.f, a1 = 0.f, a2 = 0.f;
    const float* xr = X + (size_t)row * HH;
    for (int k = lane; k < HH; k += 32) {
        float xv = xr[k];
        a0 += xv * W1[k * 3 + 0];
        a1 += xv * W1[k * 3 + 1];
        a2 += xv * W1[k * 3 + 2];
    }
    #pragma unroll
    for (int off = 16; off; off >>= 1) {
        a0 += __shfl_down_sync(0xffffffffu, a0, off);
        a1 += __shfl_down_sync(0xffffffffu, a1, off);
        a2 += __shfl_down_sync(0xffffffffu, a2, off);
    }
    if (lane == 0) {
        S[row * 3 + 0] = a0;
        S[row * 3 + 1] = a1;
        S[row * 3 + 2] = a2;
    }
}

__global__ void agg_final_kernel(const float* __restrict__ S,
                                 const float* __restrict__ b1,
                                 float* __restrict__ out) {
    int i = blockIdx.x * blockDim.x + threadIdx.x;
    if (i >= NN) return;
    float a0 = 0.f, a1 = 0.f, a2 = 0.f;
    int beg = g_rowptr[i], end = g_rowptr[i + 1];
    for (int e = beg; e < end; e++) {
        int s = g_col[e];
        float cf = g_coef[e];
        a0 += cf * S[s * 3 + 0];
        a1 += cf * S[s * 3 + 1];
        a2 += cf * S[s * 3 + 2];
    }
    out[i * 3 + 0] = a0 + b1[0];
    out[i * 3 + 1] = a1 + b1[1];
    out[i * 3 + 2] = a2 + b1[2];
}

// ---------------- host orchestration ----------------
extern "C" void kernel_launch(void* const* d_in, const int* in_sizes, int n_in,
                              void* d_out, int out_size) {
    const float* x  = (const float*)d_in[0];
    const void*  ei = d_in[1];
    const float* W0 = (const float*)d_in[2];
    const float* b0 = (const float*)d_in[3];
    const float* Wr = (const float*)d_in[4];
    const float* br = (const float*)d_in[5];
    const float* W1 = (const float*)d_in[6];
    const float* b1 = (const float*)d_in[7];
    float* out  = (float*)d_out;
    float* outX = out + (size_t)NN * CC;

    float* gS;
    __half* gX16;
    unsigned char *gA, *gW;
    int *gCnt, *gFill;
    unsigned* gIs32;
    cudaGetSymbolAddress((void**)&gX16, g_X16);
    cudaGetSymbolAddress((void**)&gS,  g_S);
    cudaGetSymbolAddress((void**)&gA,  g_A);
    cudaGetSymbolAddress((void**)&gW,  g_W);
    cudaGetSymbolAddress((void**)&gCnt, g_cnt);
    cudaGetSymbolAddress((void**)&gFill, g_fill);
    cudaGetSymbolAddress((void**)&gIs32, g_is32);

    cudaFuncSetAttribute(gemm_mma_kernel<1>,
                         cudaFuncAttributeMaxDynamicSharedMemorySize, SMEM_REQ);
    cudaFuncSetAttribute(gemm_mma_kernel<0>,
                         cudaFuncAttributeMaxDynamicSharedMemorySize, SMEM_REQ);

    // preprocessing
    cudaMemsetAsync(gCnt, 0, NN * sizeof(int));
    cudaMemsetAsync(gFill, 0, NN * sizeof(int));
    cudaMemsetAsync(gIs32, 0, sizeof(unsigned));
    detect_kernel<<<256, 256>>>((const unsigned*)ei);
    convert_count_kernel<<<(EE + 255) / 256, 256>>>(ei);
    scan_kernel<<<1, 1024>>>();
    fill_kernel<<<(EE + 255) / 256, 256>>>();
    wsplit_kernel<<<dim3(HH, 13), 64>>>(W0, Wr);

    const int nTiles = (NPAD / 128) * 4;   // 1564
    const int gGrid = 296;                 // 2 CTAs per SM

    // layer 0: agg on F=256, then GEMM K=256 -> fp16 X
    agg_kernel<<<NN, FF / 4>>>(x, gA);
    gemm_mma_kernel<1><<<gGrid, 256, SMEM_REQ>>>(gA, gW, b0, gX16, NN, nTiles, 2);

    // layers 1..11 -> fp16 X; layer 12 -> fp32 outX
    for (int L = 1; L <= 12; L++) {
        agg16_kernel<<<NN, 64>>>(gX16, gA);
        if (L == 12)
            gemm_mma_kernel<0><<<gGrid, 256, SMEM_REQ>>>(
                gA, gW + (size_t)L * WSLOT,
                br + (size_t)(L - 1) * HH, outX, NN, nTiles, 3);
        else
            gemm_mma_kernel<1><<<gGrid, 256, SMEM_REQ>>>(
                gA, gW + (size_t)L * WSLOT,
                br + (size_t)(L - 1) * HH, gX16, NN, nTiles, 3);
    }

    // final conv: GEMM first (H->3), then aggregate on 3 cols + bias
    gemm_small_kernel<<<(NN + 7) / 8, 256>>>(outX, W1, gS);
    agg_final_kernel<<<(NN + 255) / 256, 256>>>(gS, b1, out);
}

// round 10
// speedup vs baseline: 2.6796x; 1.3173x over previous
#include <cuda_runtime.h>
#include <cuda_fp16.h>
#include <cstdint>

#define NN 50000
#define EE 400000
#define FF 256
#define HH 512
#define CC 3
#define NPAD 50048                        // 391 * 128
#define CHA64 ((size_t)NPAD * 128)        // A k64-chunk stride (bytes)
#define WCH64 ((size_t)512 * 128)         // W k64-chunk stride (bytes)
#define WSLOT ((size_t)8 * 512 * 128)     // W layer slot stride (bytes)

// ---------------- device scratch ----------------
__device__ __half g_X16[(size_t)NPAD * HH];              // fp16 activations
__device__ unsigned char g_A[(size_t)8 * NPAD * 128];    // fp16 A, blocked+swizzled
__device__ unsigned char g_W[(size_t)13 * 8 * 512 * 128]; // fp16 W, blocked+swizzled
__device__ float g_S[(size_t)NN * CC];
__device__ float g_dinv[NN];
__device__ float g_coef[EE + NN];
__device__ int   g_col[EE + NN];
__device__ int   g_srcA[EE];
__device__ int   g_dstA[EE];
__device__ int   g_cnt[NN];
__device__ int   g_fill[NN];
__device__ int   g_rowptr[NN + 1];
__device__ unsigned g_is32;

// ---------------- preprocessing ----------------
__global__ void detect_kernel(const unsigned* __restrict__ w) {
    unsigned local = 0;
    for (int i = blockIdx.x * blockDim.x + threadIdx.x; i < EE;
         i += gridDim.x * blockDim.x)
        local |= w[2 * i + 1];
    #pragma unroll
    for (int off = 16; off; off >>= 1)
        local |= __shfl_xor_sync(0xffffffffu, local, off);
    if ((threadIdx.x & 31) == 0 && local) atomicOr(&g_is32, 1u);
}

__global__ void convert_count_kernel(const void* __restrict__ ei) {
    int e = blockIdx.x * blockDim.x + threadIdx.x;
    if (e >= EE) return;
    int s, d;
    if (g_is32) {
        const int* p = (const int*)ei;
        s = p[e]; d = p[EE + e];
    } else {
        const long long* p = (const long long*)ei;
        s = (int)p[e]; d = (int)p[EE + e];
    }
    g_srcA[e] = s; g_dstA[e] = d;
    atomicAdd(&g_cnt[d], 1);
}

__global__ void scan_kernel() {
    __shared__ int s[1024];
    const int T = 1024;
    int tid = threadIdx.x;
    int chunk = (NN + T - 1) / T;
    int beg = tid * chunk;
    int end = min(beg + chunk, NN);
    int sum = 0;
    for (int i = beg; i < end; i++) sum += g_cnt[i] + 1;
    s[tid] = sum;
    __syncthreads();
    for (int off = 1; off < T; off <<= 1) {
        int v = (tid >= off) ? s[tid - off] : 0;
        __syncthreads();
        s[tid] += v;
        __syncthreads();
    }
    int run = (tid > 0) ? s[tid - 1] : 0;
    for (int i = beg; i < end; i++) {
        int c = g_cnt[i];
        float di = rsqrtf((float)c + 1.0f);
        g_rowptr[i] = run;
        g_dinv[i] = di;
        g_col[run + c] = i;
        g_coef[run + c] = di * di;
        run += c + 1;
    }
    if (tid == T - 1) g_rowptr[NN] = run;
}

__global__ void fill_kernel() {
    int e = blockIdx.x * blockDim.x + threadIdx.x;
    if (e >= EE) return;
    int d = g_dstA[e], s = g_srcA[e];
    int pos = g_rowptr[d] + atomicAdd(&g_fill[d], 1);
    g_col[pos]  = s;
    g_coef[pos] = g_dinv[s] * g_dinv[d];
}

// ---------------- weight: fp16, blocked [L][kc64][n][128B], swizzled -------
__global__ void wsplit_kernel(const float* __restrict__ W0,
                              const float* __restrict__ Wr) {
    int L = blockIdx.y;
    int n = blockIdx.x;
    int K = (L == 0) ? FF : HH;
    const float* W = (L == 0) ? W0 : (Wr + (size_t)(L - 1) * HH * HH);
    unsigned char* slot = g_W + (size_t)L * WSLOT;
    int t = threadIdx.x;
    if (t >= (K >> 3)) return;
    int kc = t >> 3, u = t & 7, k0 = t * 8;
    unsigned w[4];
    #pragma unroll
    for (int p = 0; p < 4; p++) {
        unsigned lo = (unsigned)__half_as_ushort(
            __float2half_rn(W[(size_t)(k0 + 2 * p) * HH + n]));
        unsigned hi = (unsigned)__half_as_ushort(
            __float2half_rn(W[(size_t)(k0 + 2 * p + 1) * HH + n]));
        w[p] = lo | (hi << 16);
    }
    unsigned char* base = slot + (size_t)kc * WCH64 + (size_t)n * 128;
    uint32_t phys = ((uint32_t)(u ^ (n & 7))) << 4;
    *(uint4*)(base + phys) = make_uint4(w[0], w[1], w[2], w[3]);
}

// ---------------- fp32 -> fp16 convert (layer-0 input x) ----------------
__global__ void xcvt_kernel(const float* __restrict__ X, __half* __restrict__ Y) {
    size_t i = (size_t)blockIdx.x * blockDim.x + threadIdx.x;   // 8 floats each
    if (i >= (size_t)NN * FF / 8) return;
    const float4* src = (const float4*)X + 2 * i;
    float4 a = src[0], b = src[1];
    __half2 p0 = __floats2half2_rn(a.x, a.y);
    __half2 p1 = __floats2half2_rn(a.z, a.w);
    __half2 p2 = __floats2half2_rn(b.x, b.y);
    __half2 p3 = __floats2half2_rn(b.z, b.w);
    uint4 o;
    o.x = *(unsigned*)&p0; o.y = *(unsigned*)&p1;
    o.z = *(unsigned*)&p2; o.w = *(unsigned*)&p3;
    ((uint4*)Y)[i] = o;
}

// ---------------- aggregation (fp16 X) -> fp16 blocked A ----------------
// RS = row stride in uint4 units (K/8); blockDim.x == RS
template <int RS>
__global__ void agg16_kernel(const __half* __restrict__ X,
                             unsigned char* __restrict__ gA) {
    int node = blockIdx.x;
    int t = threadIdx.x;
    const uint4* Xv = (const uint4*)X;
    float acc[8];
    #pragma unroll
    for (int i = 0; i < 8; i++) acc[i] = 0.f;
    int beg = g_rowptr[node], end = g_rowptr[node + 1];
    for (int e = beg; e < end; e++) {
        int s = g_col[e];
        float cf = g_coef[e];
        uint4 v = Xv[(size_t)s * RS + t];
        float2 f0 = __half22float2(*(__half2*)&v.x);
        float2 f1 = __half22float2(*(__half2*)&v.y);
        float2 f2 = __half22float2(*(__half2*)&v.z);
        float2 f3 = __half22float2(*(__half2*)&v.w);
        acc[0] += cf * f0.x; acc[1] += cf * f0.y;
        acc[2] += cf * f1.x; acc[3] += cf * f1.y;
        acc[4] += cf * f2.x; acc[5] += cf * f2.y;
        acc[6] += cf * f3.x; acc[7] += cf * f3.y;
    }
    uint4 ph;
    {
        __half2 p0 = __floats2half2_rn(acc[0], acc[1]);
        __half2 p1 = __floats2half2_rn(acc[2], acc[3]);
        __half2 p2 = __floats2half2_rn(acc[4], acc[5]);
        __half2 p3 = __floats2half2_rn(acc[6], acc[7]);
        ph.x = *(unsigned*)&p0; ph.y = *(unsigned*)&p1;
        ph.z = *(unsigned*)&p2; ph.w = *(unsigned*)&p3;
    }
    int kc = t >> 3;
    int u  = t & 7;
    unsigned char* base = gA + (size_t)kc * CHA64 + (size_t)node * 128;
    uint32_t phys = ((uint32_t)(u ^ (node & 7))) << 4;
    *(uint4*)(base + phys) = ph;
}

// ---------------- persistent HMMA fp16 GEMM, TMA bulk, 3-stage ring -------
#define STG_B   32768
#define SMEM_REQ (1024 + 128 + 3 * STG_B)

#define MMA_F16(cc, A0, A1, A2, A3, B0, B1)                                   \
    asm volatile(                                                             \
        "mma.sync.aligned.m16n8k16.row.col.f32.f16.f16.f32 "                  \
        "{%0,%1,%2,%3}, {%4,%5,%6,%7}, {%8,%9}, {%0,%1,%2,%3};"               \
        : "+f"(cc[0]), "+f"(cc[1]), "+f"(cc[2]), "+f"(cc[3])                  \
        : "r"(A0), "r"(A1), "r"(A2), "r"(A3), "r"(B0), "r"(B1))

#define LDSM4(r0, r1, r2, r3, addr)                                           \
    asm volatile("ldmatrix.sync.aligned.m8n8.x4.shared.b16 {%0,%1,%2,%3}, [%4];" \
        : "=r"(r0), "=r"(r1), "=r"(r2), "=r"(r3) : "r"(addr))

__device__ __forceinline__ void mbar_wait(uint32_t mb, uint32_t parity) {
    uint32_t done;
    asm volatile("{\n\t.reg .pred p;\n\t"
                 "mbarrier.try_wait.parity.shared.b64 p, [%1], %2;\n\t"
                 "selp.b32 %0, 1, 0, p;\n\t}"
                 : "=r"(done) : "r"(mb), "r"(parity) : "memory");
    if (!done) {
        asm volatile("{\n\t.reg .pred P1;\n\t"
                     "WL_%=:\n\t"
                     "mbarrier.try_wait.parity.shared.b64 P1, [%0], %1;\n\t"
                     "@P1 bra.uni WD_%=;\n\t"
                     "bra.uni WL_%=;\n\t"
                     "WD_%=:\n\t}" :: "r"(mb), "r"(parity) : "memory");
    }
}

template <int OUT16>
__global__ void __launch_bounds__(256, 2) gemm_mma_kernel(
    const unsigned char* __restrict__ gA,
    const unsigned char* __restrict__ gW,
    const float* __restrict__ bias, void* __restrict__ XoutV,
    int M, int nTiles, int kshift) {
    extern __shared__ char smb[];
    uint32_t sraw;
    asm("{ .reg .u64 t; cvta.to.shared.u64 t, %1; cvt.u32.u64 %0, t; }"
        : "=r"(sraw) : "l"(smb));
    const uint32_t sb = (sraw + 1023) & ~1023u;
    const uint32_t bufBase = sb + 128;

    const int tid = threadIdx.x;
    const int lane = tid & 31, wid = tid >> 5;
    const int g = lane >> 2, t4 = lane & 3;
    const int warpM = wid & 1, warpN = wid >> 1;
    const int kmask = (1 << kshift) - 1;
    const int myTiles = (nTiles - blockIdx.x + gridDim.x - 1) / gridDim.x;
    const int totalSlots = myTiles << kshift;

    const int rx = lane & 7;
    const int aLRow = (lane & 7) + ((lane >> 3) & 1) * 8;
    const int colA = (lane >> 4) & 1;
    const int bLRow = (lane & 7) + ((lane >> 4) & 1) * 8;
    const int colB = (lane >> 3) & 1;
    const uint32_t aRowOff = (uint32_t)(warpM * 64 + aLRow) * 128;
    const uint32_t bRowOff = 16384u + (uint32_t)(warpN * 32 + bLRow) * 128;
    uint32_t pA[4], pB[4];
    #pragma unroll
    for (int j = 0; j < 4; j++) {
        pA[j] = (uint32_t)(((2 * j + colA) ^ rx) << 4);
        pB[j] = (uint32_t)(((2 * j + colB) ^ rx) << 4);
    }

    float acc[4][4][4];
    #pragma unroll
    for (int i = 0; i < 4; i++)
        #pragma unroll
        for (int j = 0; j < 4; j++)
            #pragma unroll
            for (int v = 0; v < 4; v++) acc[i][j][v] = 0.f;

    #define DECODE(s, cc, mB, nB) do {                                         \
        int tI_ = (s) >> kshift;                                               \
        int tile_ = blockIdx.x + tI_ * gridDim.x;                              \
        cc = (s) & kmask;                                                      \
        nB = (tile_ & 3) << 7;                                                 \
        mB = (tile_ >> 2) << 7;                                                \
    } while (0)

    #define FILL(stage, cc, mB, nB) do {                                       \
        uint32_t mb_ = sb + (stage) * 8;                                       \
        asm volatile("mbarrier.arrive.expect_tx.shared.b64 _, [%0], %1;"       \
            :: "r"(mb_), "r"(32768u) : "memory");                              \
        uint32_t d_ = bufBase + (stage) * STG_B;                               \
        asm volatile(                                                          \
            "cp.async.bulk.shared::cta.global.mbarrier::complete_tx::bytes "   \
            "[%0], [%1], %2, [%3];"                                            \
            :: "r"(d_), "l"(gA + (size_t)(cc) * CHA64 + (size_t)(mB) * 128),   \
               "r"(16384u), "r"(mb_) : "memory");                              \
        asm volatile(                                                          \
            "cp.async.bulk.shared::cta.global.mbarrier::complete_tx::bytes "   \
            "[%0], [%1], %2, [%3];"                                            \
            :: "r"(d_ + 16384u),                                               \
               "l"(gW + (size_t)(cc) * WCH64 + (size_t)(nB) * 128),            \
               "r"(16384u), "r"(mb_) : "memory");                              \
    } while (0)

    if (tid == 0) {
        asm volatile("mbarrier.init.shared.b64 [%0], 1;" :: "r"(sb) : "memory");
        asm volatile("mbarrier.init.shared.b64 [%0], 1;" :: "r"(sb + 8) : "memory");
        asm volatile("mbarrier.init.shared.b64 [%0], 1;" :: "r"(sb + 16) : "memory");
    }
    __syncthreads();
    if (tid == 0) {
        int c0, m0, n0; DECODE(0, c0, m0, n0); FILL(0, c0, m0, n0);
        if (totalSlots > 1) { int c1, m1, n1; DECODE(1, c1, m1, n1); FILL(1, c1, m1, n1); }
    }

    int ph[3] = {0, 0, 0};
    int stage = 0;
    for (int s = 0; s < totalSlots; s++) {
        mbar_wait(sb + stage * 8, ph[stage]);
        ph[stage] ^= 1;

        const uint32_t stA = bufBase + stage * STG_B;
        #pragma unroll
        for (int j = 0; j < 4; j++) {                  // kk16 within k64
            uint32_t bh[4][2];
            #pragma unroll
            for (int jp = 0; jp < 2; jp++) {
                uint32_t ba = stA + bRowOff + jp * 2048u + pB[j];
                LDSM4(bh[2 * jp][0], bh[2 * jp][1],
                      bh[2 * jp + 1][0], bh[2 * jp + 1][1], ba);
            }
            #pragma unroll
            for (int i = 0; i < 4; i++) {
                uint32_t aa = stA + aRowOff + i * 2048u + pA[j];
                uint32_t a0, a1, a2, a3;
                LDSM4(a0, a1, a2, a3, aa);
                #pragma unroll
                for (int jn = 0; jn < 4; jn++)
                    MMA_F16(acc[i][jn], a0, a1, a2, a3, bh[jn][0], bh[jn][1]);
            }
        }

        if ((s & kmask) == kmask) {
            int cE, mB, nB;
            DECODE(s, cE, mB, nB);
            #pragma unroll
            for (int j = 0; j < 4; j++) {
                int col = nB + warpN * 32 + j * 8 + 2 * t4;
                float bv0 = __ldg(&bias[col]), bv1 = __ldg(&bias[col + 1]);
                #pragma unroll
                for (int i = 0; i < 4; i++) {
                    int r0 = mB + warpM * 64 + i * 16 + g;
                    int r1 = r0 + 8;
                    if (OUT16) {
                        __half* Xout = (__half*)XoutV;
                        if (r0 < M) {
                            __half2 v0 = __floats2half2_rn(
                                fmaxf(acc[i][j][0] + bv0, 0.f),
                                fmaxf(acc[i][j][1] + bv1, 0.f));
                            *(__half2*)(Xout + (size_t)r0 * HH + col) = v0;
                        }
                        if (r1 < M) {
                            __half2 v1 = __floats2half2_rn(
                                fmaxf(acc[i][j][2] + bv0, 0.f),
                                fmaxf(acc[i][j][3] + bv1, 0.f));
                            *(__half2*)(Xout + (size_t)r1 * HH + col) = v1;
                        }
                    } else {
                        float* Xout = (float*)XoutV;
                        if (r0 < M) {
                            float2 v0 = make_float2(fmaxf(acc[i][j][0] + bv0, 0.f),
                                                    fmaxf(acc[i][j][1] + bv1, 0.f));
                            *(float2*)(Xout + (size_t)r0 * HH + col) = v0;
                        }
                        if (r1 < M) {
                            float2 v1 = make_float2(fmaxf(acc[i][j][2] + bv0, 0.f),
                                                    fmaxf(acc[i][j][3] + bv1, 0.f));
                            *(float2*)(Xout + (size_t)r1 * HH + col) = v1;
                        }
                    }
                    #pragma unroll
                    for (int v = 0; v < 4; v++) acc[i][j][v] = 0.f;
                }
            }
        }
        __syncthreads();
        if (tid == 0 && s + 2 < totalSlots) {
            int cN, mN, nN;
            DECODE(s + 2, cN, mN, nN);
            int nstage = stage + 2; if (nstage >= 3) nstage -= 3;
            FILL(nstage, cN, mN, nN);
        }
        stage++; if (stage >= 3) stage = 0;
    }
}

// ---------------- final small GEMM + final aggregation ----------------
__global__ void gemm_small_kernel(const float* __restrict__ X,
                                  const float* __restrict__ W1,
                                  float* __restrict__ S) {
    int row = blockIdx.x * (blockDim.x / 32) + (threadIdx.x >> 5);
    int lane = threadIdx.x & 31;
    if (row >= NN) return;
    float a0 = 0.f, a1 = 0.f, a2 = 0.f;
    const float* xr = X + (size_t)row * HH;
    for (int k = lane; k < HH; k += 32) {
        float xv = xr[k];
        a0 += xv * W1[k * 3 + 0];
        a1 += xv * W1[k * 3 + 1];
        a2 += xv * W1[k * 3 + 2];
    }
    #pragma unroll
    for (int off = 16; off; off >>= 1) {
        a0 += __shfl_down_sync(0xffffffffu, a0, off);
        a1 += __shfl_down_sync(0xffffffffu, a1, off);
        a2 += __shfl_down_sync(0xffffffffu, a2, off);
    }
    if (lane == 0) {
        S[row * 3 + 0] = a0;
        S[row * 3 + 1] = a1;
        S[row * 3 + 2] = a2;
    }
}

__global__ void agg_final_kernel(const float* __restrict__ S,
                                 const float* __restrict__ b1,
                                 float* __restrict__ out) {
    int i = blockIdx.x * blockDim.x + threadIdx.x;
    if (i >= NN) return;
    float a0 = 0.f, a1 = 0.f, a2 = 0.f;
    int beg = g_rowptr[i], end = g_rowptr[i + 1];
    for (int e = beg; e < end; e++) {
        int s = g_col[e];
        float cf = g_coef[e];
        a0 += cf * S[s * 3 + 0];
        a1 += cf * S[s * 3 + 1];
        a2 += cf * S[s * 3 + 2];
    }
    out[i * 3 + 0] = a0 + b1[0];
    out[i * 3 + 1] = a1 + b1[1];
    out[i * 3 + 2] = a2 + b1[2];
}

// ---------------- host orchestration ----------------
extern "C" void kernel_launch(void* const* d_in, const int* in_sizes, int n_in,
                              void* d_out, int out_size) {
    const float* x  = (const float*)d_in[0];
    const void*  ei = d_in[1];
    const float* W0 = (const float*)d_in[2];
    const float* b0 = (const float*)d_in[3];
    const float* Wr = (const float*)d_in[4];
    const float* br = (const float*)d_in[5];
    const float* W1 = (const float*)d_in[6];
    const float* b1 = (const float*)d_in[7];
    float* out  = (float*)d_out;
    float* outX = out + (size_t)NN * CC;

    float* gS;
    __half* gX16;
    unsigned char *gA, *gW;
    int *gCnt, *gFill;
    unsigned* gIs32;
    cudaGetSymbolAddress((void**)&gX16, g_X16);
    cudaGetSymbolAddress((void**)&gS,  g_S);
    cudaGetSymbolAddress((void**)&gA,  g_A);
    cudaGetSymbolAddress((void**)&gW,  g_W);
    cudaGetSymbolAddress((void**)&gCnt, g_cnt);
    cudaGetSymbolAddress((void**)&gFill, g_fill);
    cudaGetSymbolAddress((void**)&gIs32, g_is32);

    cudaFuncSetAttribute(gemm_mma_kernel<1>,
                         cudaFuncAttributeMaxDynamicSharedMemorySize, SMEM_REQ);
    cudaFuncSetAttribute(gemm_mma_kernel<0>,
                         cudaFuncAttributeMaxDynamicSharedMemorySize, SMEM_REQ);

    // preprocessing
    cudaMemsetAsync(gCnt, 0, NN * sizeof(int));
    cudaMemsetAsync(gFill, 0, NN * sizeof(int));
    cudaMemsetAsync(gIs32, 0, sizeof(unsigned));
    detect_kernel<<<256, 256>>>((const unsigned*)ei);
    convert_count_kernel<<<(EE + 255) / 256, 256>>>(ei);
    scan_kernel<<<1, 1024>>>();
    fill_kernel<<<(EE + 255) / 256, 256>>>();
    wsplit_kernel<<<dim3(HH, 13), 64>>>(W0, Wr);
    xcvt_kernel<<<(NN * FF / 8 + 255) / 256, 256>>>(x, gX16);

    const int nTiles = (NPAD / 128) * 4;   // 1564
    const int gGrid = 296;                 // 2 CTAs per SM

    // layer 0: agg on F=256 (fp16), then GEMM K=256 -> fp16 X
    agg16_kernel<FF / 8><<<NN, FF / 8>>>(gX16, gA);
    gemm_mma_kernel<1><<<gGrid, 256, SMEM_REQ>>>(gA, gW, b0, gX16, NN, nTiles, 2);

    // layers 1..11 -> fp16 X; layer 12 -> fp32 outX
    for (int L = 1; L <= 12; L++) {
        agg16_kernel<HH / 8><<<NN, HH / 8>>>(gX16, gA);
        if (L == 12)
            gemm_mma_kernel<0><<<gGrid, 256, SMEM_REQ>>>(
                gA, gW + (size_t)L * WSLOT,
                br + (size_t)(L - 1) * HH, outX, NN, nTiles, 3);
        else
            gemm_mma_kernel<1><<<gGrid, 256, SMEM_REQ>>>(
                gA, gW + (size_t)L * WSLOT,
                br + (size_t)(L - 1) * HH, gX16, NN, nTiles, 3);
    }

    // final conv: GEMM first (H->3), then aggregate on 3 cols + bias
    gemm_small_kernel<<<(NN + 7) / 8, 256>>>(outX, W1, gS);
    agg_final_kernel<<<(NN + 255) / 256, 256>>>(gS, b1, out);
}